// round 4
// baseline (speedup 1.0000x reference)
#include <cuda_runtime.h>
#include <math.h>

#define B_ 128
#define T_ 64
#define F_ 2048
#define H_ 1024
#define M_ 512
#define G4_ (4 * H_)   // 4096

// ---------------- scratch (static __device__ globals; no cudaMalloc allowed) ---
__device__ float g_V[B_ * T_ * H_];                 // embedded frames, row r = b*T + t
__device__ float g_A1[(size_t)B_ * T_ * G4_];       // x @ W_ih1^T + b1, row r = b*T + t
__device__ float g_abd[B_ * T_];                    // x . (Wsi^T vs) + b_bd . vs
__device__ float g_wsiv[H_];                        // Wsi^T vs
__device__ float g_wshv[H_];                        // Wsh^T vs
__device__ float g_bb;                              // b_bd . vs
__device__ float g_h1[2][B_ * H_];
__device__ float g_h2[2][B_ * H_];
__device__ float g_c1[B_ * H_];
__device__ float g_c2[B_ * H_];
__device__ float g_x2[B_ * H_];                     // h1_new * s  (input to LSTM2)
__device__ float g_s[B_];                           // binarized boundary gate

__device__ __forceinline__ float sigf(float x) { return 1.0f / (1.0f + expf(-x)); }

// ---------------- K0: vs-projections of the boundary detector ------------------
__global__ void k_proj(const float* __restrict__ Wsi, const float* __restrict__ Wsh,
                       const float* __restrict__ b_bd, const float* __restrict__ vs) {
    int blk = blockIdx.x;
    if (blk < 8) {
        int h = blk * 128 + threadIdx.x;
        float s1 = 0.f, s2 = 0.f;
        for (int m = 0; m < M_; m++) {
            float v = vs[m];
            s1 += Wsi[m * H_ + h] * v;
            s2 += Wsh[m * H_ + h] * v;
        }
        g_wsiv[h] = s1;
        g_wshv[h] = s2;
    } else {
        __shared__ float red[128];
        float s = 0.f;
        for (int m = threadIdx.x; m < M_; m += 128) s += b_bd[m] * vs[m];
        red[threadIdx.x] = s;
        __syncthreads();
        for (int st = 64; st > 0; st >>= 1) {
            if (threadIdx.x < st) red[threadIdx.x] += red[threadIdx.x + st];
            __syncthreads();
        }
        if (threadIdx.x == 0) g_bb = red[0];
    }
}

// ---------------- generic tiled GEMM: C[M,N] = A[M,K] * B[N,K]^T (+bias)(+relu) -
// BM=128, BN=64, BK=16, TM=8, TN=4, 256 threads.
template <bool RELU, bool BIAS>
__global__ void gemm_abt(const float* __restrict__ A, const float* __restrict__ Bm,
                         const float* __restrict__ bias, float* __restrict__ C,
                         int M, int N, int K) {
    __shared__ float As[16][128];
    __shared__ float Bs[16][64];

    int tid = threadIdx.x;
    int tx = tid & 15;          // N direction, TN=4
    int ty = tid >> 4;          // M direction, TM=8
    int bn0 = blockIdx.x * 64;
    int bm0 = blockIdx.y * 128;

    const float* Ab = A + (size_t)bm0 * K;
    const float* Bb = Bm + (size_t)bn0 * K;

    float acc[8][4];
#pragma unroll
    for (int i = 0; i < 8; i++)
#pragma unroll
        for (int j = 0; j < 4; j++) acc[i][j] = 0.f;

    int lr = tid >> 2;            // 0..63
    int lc = (tid & 3) * 4;       // 0,4,8,12

    for (int k0 = 0; k0 < K; k0 += 16) {
        // A tile: 128 rows x 16 cols, 2 float4 per thread
        float4 va = *(const float4*)(Ab + (size_t)lr * K + k0 + lc);
        float4 wa = *(const float4*)(Ab + (size_t)(lr + 64) * K + k0 + lc);
        // B tile: 64 rows x 16 cols, 1 float4 per thread
        float4 vb = *(const float4*)(Bb + (size_t)lr * K + k0 + lc);

        As[lc + 0][lr] = va.x; As[lc + 1][lr] = va.y; As[lc + 2][lr] = va.z; As[lc + 3][lr] = va.w;
        As[lc + 0][lr + 64] = wa.x; As[lc + 1][lr + 64] = wa.y; As[lc + 2][lr + 64] = wa.z; As[lc + 3][lr + 64] = wa.w;
        Bs[lc + 0][lr] = vb.x; Bs[lc + 1][lr] = vb.y; Bs[lc + 2][lr] = vb.z; Bs[lc + 3][lr] = vb.w;
        __syncthreads();

#pragma unroll
        for (int k = 0; k < 16; k++) {
            float4 a0 = *(const float4*)&As[k][ty * 8];
            float4 a1 = *(const float4*)&As[k][ty * 8 + 4];
            float4 bv = *(const float4*)&Bs[k][tx * 4];
            float a[8] = {a0.x, a0.y, a0.z, a0.w, a1.x, a1.y, a1.z, a1.w};
            float b[4] = {bv.x, bv.y, bv.z, bv.w};
#pragma unroll
            for (int i = 0; i < 8; i++)
#pragma unroll
                for (int j = 0; j < 4; j++) acc[i][j] += a[i] * b[j];
        }
        __syncthreads();
    }

#pragma unroll
    for (int i = 0; i < 8; i++) {
        int row = bm0 + ty * 8 + i;
        int col = bn0 + tx * 4;
        float4 v;
        v.x = acc[i][0]; v.y = acc[i][1]; v.z = acc[i][2]; v.w = acc[i][3];
        if (BIAS) {
            v.x += bias[col + 0]; v.y += bias[col + 1];
            v.z += bias[col + 2]; v.w += bias[col + 3];
        }
        if (RELU) {
            v.x = fmaxf(v.x, 0.f); v.y = fmaxf(v.y, 0.f);
            v.z = fmaxf(v.z, 0.f); v.w = fmaxf(v.w, 0.f);
        }
        *(float4*)(C + (size_t)row * N + col) = v;
    }
}

// ---------------- K3: abd[r] = V[r] . wsiv + bb  (one warp per row) ------------
__global__ void k_abd() {
    int r = blockIdx.x * 8 + (threadIdx.x >> 5);
    int lane = threadIdx.x & 31;
    const float* vr = g_V + (size_t)r * H_;
    float s = 0.f;
    for (int h = lane; h < H_; h += 32) s += vr[h] * g_wsiv[h];
#pragma unroll
    for (int o = 16; o > 0; o >>= 1) s += __shfl_xor_sync(0xffffffffu, s, o);
    if (lane == 0) g_abd[r] = s + g_bb;
}

// ---------------- init: zero state + initial gate s for t=0 --------------------
__global__ void k_init() {
    int i = blockIdx.x * blockDim.x + threadIdx.x;
    if (i < B_ * H_) {
        g_h1[0][i] = 0.f; g_c1[i] = 0.f;
        g_h2[0][i] = 0.f; g_c2[i] = 0.f;
    }
    // t=0: h1 = 0, so u = abd[b*T + 0]; compute s directly
    if (i < B_) {
        float z = 1.0f / (1.0f + expf(-g_abd[i * T_]));
        g_s[i] = rintf(z);
    }
}

// ---------------- per-step: gates1 GEMM + LSTM1 + boundary masking --------------
// Block owns 8 hidden cols (all 4 gates), all 128 batch rows. grid = 128 blocks.
__global__ void k_lstm1(const float* __restrict__ Whh1, int t, int rb) {
    __shared__ float As[16][128];
    __shared__ float Bs[16][32];

    int tid = threadIdx.x;
    int lane = tid & 31;      // 4 batch rows each: b = lane*4 + mi
    int wid = tid >> 5;       // hidden col within slice (0..7)
    int hb = blockIdx.x * 8;
    const float* h1r = g_h1[rb];

    float acc[4][4];          // [mi][gate]
#pragma unroll
    for (int i = 0; i < 4; i++)
#pragma unroll
        for (int j = 0; j < 4; j++) acc[i][j] = 0.f;

    int lr = tid >> 2;        // 0..63
    int lc = (tid & 3) * 4;

    for (int k0 = 0; k0 < H_; k0 += 16) {
        float4 va = *(const float4*)(h1r + (size_t)lr * H_ + k0 + lc);
        float4 wa = *(const float4*)(h1r + (size_t)(lr + 64) * H_ + k0 + lc);
        As[lc + 0][lr] = va.x; As[lc + 1][lr] = va.y; As[lc + 2][lr] = va.z; As[lc + 3][lr] = va.w;
        As[lc + 0][lr + 64] = wa.x; As[lc + 1][lr + 64] = wa.y; As[lc + 2][lr + 64] = wa.z; As[lc + 3][lr + 64] = wa.w;
        if (tid < 128) {
            int np = tid >> 2;          // 0..31 : np = gate*8 + col
            int g = np >> 3, c = np & 7;
            const float* Br = Whh1 + (size_t)(g * H_ + hb + c) * H_;
            float4 vb = *(const float4*)(Br + k0 + lc);
            Bs[lc + 0][np] = vb.x; Bs[lc + 1][np] = vb.y; Bs[lc + 2][np] = vb.z; Bs[lc + 3][np] = vb.w;
        }
        __syncthreads();
#pragma unroll
        for (int k = 0; k < 16; k++) {
            float4 a = *(const float4*)&As[k][lane * 4];
            float b0 = Bs[k][wid], b1 = Bs[k][8 + wid], b2 = Bs[k][16 + wid], b3 = Bs[k][24 + wid];
            acc[0][0] += a.x * b0; acc[1][0] += a.y * b0; acc[2][0] += a.z * b0; acc[3][0] += a.w * b0;
            acc[0][1] += a.x * b1; acc[1][1] += a.y * b1; acc[2][1] += a.z * b1; acc[3][1] += a.w * b1;
            acc[0][2] += a.x * b2; acc[1][2] += a.y * b2; acc[2][2] += a.z * b2; acc[3][2] += a.w * b2;
            acc[0][3] += a.x * b3; acc[1][3] += a.y * b3; acc[2][3] += a.z * b3; acc[3][3] += a.w * b3;
        }
        __syncthreads();
    }

    int h = hb + wid;
    int wb = rb ^ 1;
#pragma unroll
    for (int mi = 0; mi < 4; mi++) {
        int b = lane * 4 + mi;
        const float* a1 = g_A1 + (size_t)(b * T_ + t) * G4_;
        float gi = acc[mi][0] + a1[h];
        float gf = acc[mi][1] + a1[1024 + h];
        float gg = acc[mi][2] + a1[2048 + h];
        float go = acc[mi][3] + a1[3072 + h];
        float c_old = g_c1[b * H_ + h];
        float cn = sigf(gf) * c_old + sigf(gi) * tanhf(gg);
        float hn = sigf(go) * tanhf(cn);
        float s = g_s[b];
        g_x2[b * H_ + h] = hn * s;
        g_h1[wb][b * H_ + h] = hn * (1.0f - s);
        g_c1[b * H_ + h] = cn * (1.0f - s);
    }
}

// ---------------- per-step: gates2 (concat-K) GEMM + LSTM2 ----------------------
// Blocks [0,128): lstm2 GEMM+pointwise. Blocks [128,144): boundary gate s for
// step t+1 (reads g_h1[rb^1], written by k_lstm1(t) which precedes us in-stream;
// g_s was already consumed by k_lstm1(t)'s epilogue, so overwriting is safe).
__global__ void k_lstm2(const float* __restrict__ Wih2, const float* __restrict__ Whh2,
                        int t, int rb, float* __restrict__ out2) {
    if (blockIdx.x >= H_ / 8) {
        // ---- fused k_z for step t+1 ----
        if (t + 1 >= T_) return;
        int b = (blockIdx.x - H_ / 8) * 8 + (threadIdx.x >> 5);
        int lane = threadIdx.x & 31;
        const float* h1 = g_h1[rb ^ 1] + (size_t)b * H_;
        float u = 0.f;
        for (int h = lane; h < H_; h += 32) u += h1[h] * g_wshv[h];
#pragma unroll
        for (int o = 16; o > 0; o >>= 1) u += __shfl_xor_sync(0xffffffffu, u, o);
        if (lane == 0) {
            u += g_abd[b * T_ + t + 1];
            float z = 1.0f / (1.0f + expf(-u));
            g_s[b] = rintf(z);   // round-half-even, matches jnp.round
        }
        return;
    }

    __shared__ float As[16][128];
    __shared__ float Bs[16][32];

    int tid = threadIdx.x;
    int lane = tid & 31;
    int wid = tid >> 5;
    int hb = blockIdx.x * 8;

    float acc[4][4];
#pragma unroll
    for (int i = 0; i < 4; i++)
#pragma unroll
        for (int j = 0; j < 4; j++) acc[i][j] = 0.f;

    int lr = tid >> 2;
    int lc = (tid & 3) * 4;
    const float* h2r = g_h2[rb];

    for (int k0 = 0; k0 < 2 * H_; k0 += 16) {
        const float* Abase = (k0 < H_) ? g_x2 : h2r;
        const float* Bbase = (k0 < H_) ? Wih2 : Whh2;
        int kc = (k0 < H_) ? k0 : (k0 - H_);

        float4 va = *(const float4*)(Abase + (size_t)lr * H_ + kc + lc);
        float4 wa = *(const float4*)(Abase + (size_t)(lr + 64) * H_ + kc + lc);
        As[lc + 0][lr] = va.x; As[lc + 1][lr] = va.y; As[lc + 2][lr] = va.z; As[lc + 3][lr] = va.w;
        As[lc + 0][lr + 64] = wa.x; As[lc + 1][lr + 64] = wa.y; As[lc + 2][lr + 64] = wa.z; As[lc + 3][lr + 64] = wa.w;
        if (tid < 128) {
            int np = tid >> 2;
            int g = np >> 3, c = np & 7;
            const float* Br = Bbase + (size_t)(g * H_ + hb + c) * H_;
            float4 vb = *(const float4*)(Br + kc + lc);
            Bs[lc + 0][np] = vb.x; Bs[lc + 1][np] = vb.y; Bs[lc + 2][np] = vb.z; Bs[lc + 3][np] = vb.w;
        }
        __syncthreads();
#pragma unroll
        for (int k = 0; k < 16; k++) {
            float4 a = *(const float4*)&As[k][lane * 4];
            float b0 = Bs[k][wid], b1 = Bs[k][8 + wid], b2 = Bs[k][16 + wid], b3 = Bs[k][24 + wid];
            acc[0][0] += a.x * b0; acc[1][0] += a.y * b0; acc[2][0] += a.z * b0; acc[3][0] += a.w * b0;
            acc[0][1] += a.x * b1; acc[1][1] += a.y * b1; acc[2][1] += a.z * b1; acc[3][1] += a.w * b1;
            acc[0][2] += a.x * b2; acc[1][2] += a.y * b2; acc[2][2] += a.z * b2; acc[3][2] += a.w * b2;
            acc[0][3] += a.x * b3; acc[1][3] += a.y * b3; acc[2][3] += a.z * b3; acc[3][3] += a.w * b3;
        }
        __syncthreads();
    }

    int h = hb + wid;
    int wb = rb ^ 1;
#pragma unroll
    for (int mi = 0; mi < 4; mi++) {
        int b = lane * 4 + mi;
        float gi = acc[mi][0];
        float gf = acc[mi][1];
        float gg = acc[mi][2];
        float go = acc[mi][3];
        float c_old = g_c2[b * H_ + h];
        float cn = sigf(gf) * c_old + sigf(gi) * tanhf(gg);
        float hn = sigf(go) * tanhf(cn);
        g_h2[wb][b * H_ + h] = hn;
        g_c2[b * H_ + h] = cn;
        if (out2) out2[b * H_ + h] = hn;
    }
}

// ---------------- launch --------------------------------------------------------
extern "C" void kernel_launch(void* const* d_in, const int* in_sizes, int n_in,
                              void* d_out, int out_size) {
    const float* video   = (const float*)d_in[0];
    const float* W_embed = (const float*)d_in[1];
    const float* b_embed = (const float*)d_in[2];
    const float* W_ih1   = (const float*)d_in[3];
    const float* W_hh1   = (const float*)d_in[4];
    const float* b1      = (const float*)d_in[5];
    const float* Wsi     = (const float*)d_in[6];
    const float* Wsh     = (const float*)d_in[7];
    const float* b_bd    = (const float*)d_in[8];
    const float* vs      = (const float*)d_in[9];
    const float* W_ih2   = (const float*)d_in[10];
    const float* W_hh2   = (const float*)d_in[11];
    float* out = (float*)d_out;

    float *pV = nullptr, *pA1 = nullptr;
    cudaGetSymbolAddress((void**)&pV, g_V);
    cudaGetSymbolAddress((void**)&pA1, g_A1);

    // boundary-detector vs-projections (kills M=512 dim from the recurrence)
    k_proj<<<9, 128>>>(Wsi, Wsh, b_bd, vs);

    // embed: V = relu(video @ W_embed^T + b_embed)   [8192 x 1024], K=2048
    gemm_abt<true, true><<<dim3(1024 / 64, (B_ * T_) / 128), 256>>>(
        video, W_embed, b_embed, pV, B_ * T_, H_, F_);

    // A1 = V @ W_ih1^T + b1   [8192 x 4096], K=1024
    gemm_abt<false, true><<<dim3(G4_ / 64, (B_ * T_) / 128), 256>>>(
        pV, W_ih1, b1, pA1, B_ * T_, G4_, H_);

    // abd = V . wsiv + bb
    k_abd<<<(B_ * T_) / 8, 256>>>();

    // zero state + initial boundary gate (t=0, h1=0)
    k_init<<<(B_ * H_ + 255) / 256, 256>>>();

    // sequential scan (boundary gate for t+1 fused into k_lstm2's extra blocks)
    for (int t = 0; t < T_; t++) {
        int rb = t & 1;
        k_lstm1<<<H_ / 8, 256>>>(W_hh1, t, rb);
        k_lstm2<<<H_ / 8 + B_ / 8, 256>>>(W_ih2, W_hh2, t, rb,
                                          (t == T_ - 1) ? out : nullptr);
    }
}

// round 6
// speedup vs baseline: 2.1568x; 2.1568x over previous
#include <cuda_runtime.h>
#include <cuda_bf16.h>
#include <stdint.h>
#include <math.h>

#define B_ 128
#define T_ 64
#define F_ 2048
#define H_ 1024
#define M_ 512
#define G4_ 4096
#define PAD 40

typedef __nv_bfloat16 bf16;

// ---------------- fp32 scratch ---------------------------------------------
__device__ float g_V[B_ * T_ * H_];
__device__ float g_A1[(size_t)B_ * T_ * G4_];
__device__ float g_abd[B_ * T_];
__device__ float g_wsiv[H_], g_wshv[H_];
__device__ float g_bb;
__device__ float g_h1f[2][B_ * H_];     // fp32 h1 (gate dot-product path)
__device__ float g_c1[B_ * H_], g_c2[B_ * H_];
__device__ float g_s[B_];

// ---------------- split-bf16 operands (hi + lo = ~fp32) --------------------
__device__ bf16 g_vidh[B_ * T_ * F_], g_vidl[B_ * T_ * F_];
__device__ bf16 g_Vh[B_ * T_ * H_],   g_Vl[B_ * T_ * H_];
__device__ bf16 g_Wemb_h[H_ * F_],    g_Wemb_l[H_ * F_];
__device__ bf16 g_Wih1_h[G4_ * H_],   g_Wih1_l[G4_ * H_];
__device__ bf16 g_Whh1_h[G4_ * H_],   g_Whh1_l[G4_ * H_];
__device__ bf16 g_Wih2_h[G4_ * H_],   g_Wih2_l[G4_ * H_];
__device__ bf16 g_Whh2_h[G4_ * H_],   g_Whh2_l[G4_ * H_];
__device__ bf16 g_h1h[2][B_ * H_],    g_h1l[2][B_ * H_];
__device__ bf16 g_h2h[2][B_ * H_],    g_h2l[2][B_ * H_];
__device__ bf16 g_x2h[B_ * H_],       g_x2l[B_ * H_];

__device__ __forceinline__ float sigf(float x) { return 1.0f / (1.0f + expf(-x)); }

__device__ __forceinline__ void mma16816(float& c0, float& c1, float& c2, float& c3,
                                         uint32_t a0, uint32_t a1, uint32_t a2, uint32_t a3,
                                         uint32_t b0, uint32_t b1) {
    asm volatile(
        "mma.sync.aligned.m16n8k16.row.col.f32.bf16.bf16.f32 "
        "{%0,%1,%2,%3},{%4,%5,%6,%7},{%8,%9},{%0,%1,%2,%3};"
        : "+f"(c0), "+f"(c1), "+f"(c2), "+f"(c3)
        : "r"(a0), "r"(a1), "r"(a2), "r"(a3), "r"(b0), "r"(b1));
}

__device__ __forceinline__ uint32_t ld_s32(const bf16* p) { return *(const uint32_t*)p; }

__device__ __forceinline__ uint32_t pack_hi(float x, float y) {
    __nv_bfloat162 t; t.x = __float2bfloat16(x); t.y = __float2bfloat16(y);
    return *(uint32_t*)&t;
}
__device__ __forceinline__ uint32_t pack_lo(float x, float y) {
    bf16 hx = __float2bfloat16(x), hy = __float2bfloat16(y);
    __nv_bfloat162 t;
    t.x = __float2bfloat16(x - __bfloat162float(hx));
    t.y = __float2bfloat16(y - __bfloat162float(hy));
    return *(uint32_t*)&t;
}

// ---------------- split fp32 -> (hi, lo) bf16, 4 elems/thread --------------
__global__ void k_split4(const float* __restrict__ src, bf16* __restrict__ h,
                         bf16* __restrict__ l, int n4) {
    int i = blockIdx.x * blockDim.x + threadIdx.x;
    if (i >= n4) return;
    float4 v = ((const float4*)src)[i];
    uint2 hp, lp;
    hp.x = pack_hi(v.x, v.y); hp.y = pack_hi(v.z, v.w);
    lp.x = pack_lo(v.x, v.y); lp.y = pack_lo(v.z, v.w);
    ((uint2*)h)[i] = hp;
    ((uint2*)l)[i] = lp;
}

// ---------------- K0: vs-projections of boundary detector ------------------
__global__ void k_proj(const float* __restrict__ Wsi, const float* __restrict__ Wsh,
                       const float* __restrict__ b_bd, const float* __restrict__ vs) {
    int blk = blockIdx.x;
    if (blk < 8) {
        int h = blk * 128 + threadIdx.x;
        float s1 = 0.f, s2 = 0.f;
        for (int m = 0; m < M_; m++) {
            float v = vs[m];
            s1 += Wsi[m * H_ + h] * v;
            s2 += Wsh[m * H_ + h] * v;
        }
        g_wsiv[h] = s1;
        g_wshv[h] = s2;
    } else {
        __shared__ float red[128];
        float s = 0.f;
        for (int m = threadIdx.x; m < M_; m += 128) s += b_bd[m] * vs[m];
        red[threadIdx.x] = s;
        __syncthreads();
        for (int st = 64; st > 0; st >>= 1) {
            if (threadIdx.x < st) red[threadIdx.x] += red[threadIdx.x + st];
            __syncthreads();
        }
        if (threadIdx.x == 0) g_bb = red[0];
    }
}

// ---------------- precompute GEMM: C[M,N] = A[M,K]*B[N,K]^T ----------------
// split-bf16 3-term mma. BM=128, BN=64, BK=32, 256 thr, warps 2(m) x 4(n).
template <bool RELU, bool BIAS, bool SPLIT>
__global__ void mm_pre(const bf16* __restrict__ Ah, const bf16* __restrict__ Al,
                       const bf16* __restrict__ Bh, const bf16* __restrict__ Bl,
                       const float* __restrict__ bias, float* __restrict__ C,
                       bf16* __restrict__ Ch, bf16* __restrict__ Cl, int N, int K) {
    __shared__ __align__(16) bf16 As_h[128][PAD], As_l[128][PAD];
    __shared__ __align__(16) bf16 Bs_h[64][PAD],  Bs_l[64][PAD];

    int tid = threadIdx.x, lane = tid & 31, wid = tid >> 5;
    int wm = wid >> 2, wn = wid & 3;
    int gr = lane >> 2, tc = lane & 3;
    int bn0 = blockIdx.x * 64, bm0 = blockIdx.y * 128;
    int K8 = K >> 3;
    const uint4* A4h = (const uint4*)Ah; const uint4* A4l = (const uint4*)Al;
    const uint4* B4h = (const uint4*)Bh; const uint4* B4l = (const uint4*)Bl;

    float acc[4][2][4];
#pragma unroll
    for (int a = 0; a < 4; a++)
#pragma unroll
        for (int b = 0; b < 2; b++)
#pragma unroll
            for (int c = 0; c < 4; c++) acc[a][b][c] = 0.f;

    for (int k0 = 0; k0 < K; k0 += 32) {
        int kq = k0 >> 3;
#pragma unroll
        for (int rep = 0; rep < 2; rep++) {
            int u = tid + 256 * rep;
            int r = u >> 2, q = u & 3;
            *(uint4*)&As_h[r][q * 8] = A4h[(size_t)(bm0 + r) * K8 + kq + q];
            *(uint4*)&As_l[r][q * 8] = A4l[(size_t)(bm0 + r) * K8 + kq + q];
        }
        {
            int r = tid >> 2, q = tid & 3;
            *(uint4*)&Bs_h[r][q * 8] = B4h[(size_t)(bn0 + r) * K8 + kq + q];
            *(uint4*)&Bs_l[r][q * 8] = B4l[(size_t)(bn0 + r) * K8 + kq + q];
        }
        __syncthreads();
#pragma unroll
        for (int ks = 0; ks < 32; ks += 16) {
            uint32_t afh[4][4], afl[4][4];
#pragma unroll
            for (int mt = 0; mt < 4; mt++) {
                int r0 = wm * 64 + mt * 16 + gr;
                afh[mt][0] = ld_s32(&As_h[r0][ks + 2 * tc]);
                afh[mt][1] = ld_s32(&As_h[r0 + 8][ks + 2 * tc]);
                afh[mt][2] = ld_s32(&As_h[r0][ks + 2 * tc + 8]);
                afh[mt][3] = ld_s32(&As_h[r0 + 8][ks + 2 * tc + 8]);
                afl[mt][0] = ld_s32(&As_l[r0][ks + 2 * tc]);
                afl[mt][1] = ld_s32(&As_l[r0 + 8][ks + 2 * tc]);
                afl[mt][2] = ld_s32(&As_l[r0][ks + 2 * tc + 8]);
                afl[mt][3] = ld_s32(&As_l[r0 + 8][ks + 2 * tc + 8]);
            }
#pragma unroll
            for (int nt = 0; nt < 2; nt++) {
                int n0 = wn * 16 + nt * 8 + gr;
                uint32_t bh0 = ld_s32(&Bs_h[n0][ks + 2 * tc]);
                uint32_t bh1 = ld_s32(&Bs_h[n0][ks + 2 * tc + 8]);
                uint32_t bl0 = ld_s32(&Bs_l[n0][ks + 2 * tc]);
                uint32_t bl1 = ld_s32(&Bs_l[n0][ks + 2 * tc + 8]);
#pragma unroll
                for (int mt = 0; mt < 4; mt++) {
                    float* d = acc[mt][nt];
                    mma16816(d[0], d[1], d[2], d[3], afh[mt][0], afh[mt][1], afh[mt][2], afh[mt][3], bh0, bh1);
                    mma16816(d[0], d[1], d[2], d[3], afh[mt][0], afh[mt][1], afh[mt][2], afh[mt][3], bl0, bl1);
                    mma16816(d[0], d[1], d[2], d[3], afl[mt][0], afl[mt][1], afl[mt][2], afl[mt][3], bh0, bh1);
                }
            }
        }
        __syncthreads();
    }

#pragma unroll
    for (int mt = 0; mt < 4; mt++)
#pragma unroll
        for (int nt = 0; nt < 2; nt++) {
            int row0 = bm0 + wm * 64 + mt * 16 + gr;
            int col = bn0 + wn * 16 + nt * 8 + 2 * tc;
            float2 bs = BIAS ? *(const float2*)&bias[col] : make_float2(0.f, 0.f);
#pragma unroll
            for (int rs = 0; rs < 2; rs++) {
                int row = row0 + 8 * rs;
                float v0 = acc[mt][nt][2 * rs] + bs.x;
                float v1 = acc[mt][nt][2 * rs + 1] + bs.y;
                if (RELU) { v0 = fmaxf(v0, 0.f); v1 = fmaxf(v1, 0.f); }
                *(float2*)&C[(size_t)row * N + col] = make_float2(v0, v1);
                if (SPLIT) {
                    *(uint32_t*)&Ch[(size_t)row * N + col] = pack_hi(v0, v1);
                    *(uint32_t*)&Cl[(size_t)row * N + col] = pack_lo(v0, v1);
                }
            }
        }
}

// ---------------- abd[r] = V[r] . wsiv + bb --------------------------------
__global__ void k_abd() {
    int r = blockIdx.x * 8 + (threadIdx.x >> 5);
    int lane = threadIdx.x & 31;
    const float* vr = g_V + (size_t)r * H_;
    float s = 0.f;
    for (int h = lane; h < H_; h += 32) s += vr[h] * g_wsiv[h];
#pragma unroll
    for (int o = 16; o > 0; o >>= 1) s += __shfl_xor_sync(0xffffffffu, s, o);
    if (lane == 0) g_abd[r] = s + g_bb;
}

// ---------------- init: zero state + t=0 gate ------------------------------
__global__ void k_init() {
    int i = blockIdx.x * blockDim.x + threadIdx.x;
    if (i < B_ * H_) {
        g_c1[i] = 0.f; g_c2[i] = 0.f;
        g_h1h[0][i] = __float2bfloat16(0.f); g_h1l[0][i] = __float2bfloat16(0.f);
        g_h2h[0][i] = __float2bfloat16(0.f); g_h2l[0][i] = __float2bfloat16(0.f);
    }
    if (i < B_) {
        float z = 1.0f / (1.0f + expf(-g_abd[i * T_]));
        g_s[i] = rintf(z);
    }
}

// ---------------- scan: gates1 mma-GEMM + LSTM1 + masking ------------------
// Block: 8 hidden cols x 4 gates (BN=32 as 4 n8-tiles), all 128 batch rows.
// 8 warps, warp w -> m16 tile rows 16w..16w+15. grid = 128 blocks.
__global__ void k_lstm1(int t, int rb) {
    __shared__ __align__(16) bf16 As_h[128][PAD], As_l[128][PAD];
    __shared__ __align__(16) bf16 Bs_h[32][PAD],  Bs_l[32][PAD];

    int tid = threadIdx.x, lane = tid & 31, wid = tid >> 5;
    int gr = lane >> 2, tc = lane & 3;
    int hb = blockIdx.x * 8;
    const uint4* A4h = (const uint4*)g_h1h[rb];
    const uint4* A4l = (const uint4*)g_h1l[rb];
    const uint4* W4h = (const uint4*)g_Whh1_h;
    const uint4* W4l = (const uint4*)g_Whh1_l;

    float acc[4][4];
#pragma unroll
    for (int g = 0; g < 4; g++)
#pragma unroll
        for (int c = 0; c < 4; c++) acc[g][c] = 0.f;

    for (int k0 = 0; k0 < H_; k0 += 32) {
        int kq = k0 >> 3;
#pragma unroll
        for (int rep = 0; rep < 2; rep++) {
            int u = tid + 256 * rep;
            int r = u >> 2, q = u & 3;
            *(uint4*)&As_h[r][q * 8] = A4h[r * 128 + kq + q];
            *(uint4*)&As_l[r][q * 8] = A4l[r * 128 + kq + q];
        }
        if (tid < 128) {
            int r = tid >> 2, q = tid & 3;
            int wr = (r >> 3) * H_ + hb + (r & 7);
            *(uint4*)&Bs_h[r][q * 8] = W4h[(size_t)wr * 128 + kq + q];
        } else {
            int u = tid - 128;
            int r = u >> 2, q = u & 3;
            int wr = (r >> 3) * H_ + hb + (r & 7);
            *(uint4*)&Bs_l[r][q * 8] = W4l[(size_t)wr * 128 + kq + q];
        }
        __syncthreads();
#pragma unroll
        for (int ks = 0; ks < 32; ks += 16) {
            int r0 = wid * 16 + gr;
            uint32_t ah0 = ld_s32(&As_h[r0][ks + 2 * tc]);
            uint32_t ah1 = ld_s32(&As_h[r0 + 8][ks + 2 * tc]);
            uint32_t ah2 = ld_s32(&As_h[r0][ks + 2 * tc + 8]);
            uint32_t ah3 = ld_s32(&As_h[r0 + 8][ks + 2 * tc + 8]);
            uint32_t al0 = ld_s32(&As_l[r0][ks + 2 * tc]);
            uint32_t al1 = ld_s32(&As_l[r0 + 8][ks + 2 * tc]);
            uint32_t al2 = ld_s32(&As_l[r0][ks + 2 * tc + 8]);
            uint32_t al3 = ld_s32(&As_l[r0 + 8][ks + 2 * tc + 8]);
#pragma unroll
            for (int g = 0; g < 4; g++) {
                int n0 = g * 8 + gr;
                uint32_t bh0 = ld_s32(&Bs_h[n0][ks + 2 * tc]);
                uint32_t bh1 = ld_s32(&Bs_h[n0][ks + 2 * tc + 8]);
                uint32_t bl0 = ld_s32(&Bs_l[n0][ks + 2 * tc]);
                uint32_t bl1 = ld_s32(&Bs_l[n0][ks + 2 * tc + 8]);
                float* d = acc[g];
                mma16816(d[0], d[1], d[2], d[3], ah0, ah1, ah2, ah3, bh0, bh1);
                mma16816(d[0], d[1], d[2], d[3], ah0, ah1, ah2, ah3, bl0, bl1);
                mma16816(d[0], d[1], d[2], d[3], al0, al1, al2, al3, bh0, bh1);
            }
        }
        __syncthreads();
    }

    // epilogue: LSTM1 pointwise + boundary mask + split writes
    int wb = rb ^ 1;
    int h0 = hb + 2 * tc;
#pragma unroll
    for (int rs = 0; rs < 2; rs++) {
        int b = wid * 16 + gr + 8 * rs;
        float s = g_s[b];
        const float* a1 = g_A1 + (size_t)(b * T_ + t) * G4_;
        float2 ai = *(const float2*)&a1[h0];
        float2 af = *(const float2*)&a1[1024 + h0];
        float2 ag = *(const float2*)&a1[2048 + h0];
        float2 ao = *(const float2*)&a1[3072 + h0];
        int idx = b * H_ + h0;
        float2 coldp = *(const float2*)&g_c1[idx];

        float gi0 = acc[0][2 * rs] + ai.x,     gi1 = acc[0][2 * rs + 1] + ai.y;
        float gf0 = acc[1][2 * rs] + af.x,     gf1 = acc[1][2 * rs + 1] + af.y;
        float gg0 = acc[2][2 * rs] + ag.x,     gg1 = acc[2][2 * rs + 1] + ag.y;
        float go0 = acc[3][2 * rs] + ao.x,     go1 = acc[3][2 * rs + 1] + ao.y;

        float cn0 = sigf(gf0) * coldp.x + sigf(gi0) * tanhf(gg0);
        float cn1 = sigf(gf1) * coldp.y + sigf(gi1) * tanhf(gg1);
        float hn0 = sigf(go0) * tanhf(cn0);
        float hn1 = sigf(go1) * tanhf(cn1);

        float x20 = hn0 * s,            x21 = hn1 * s;
        float h10 = hn0 * (1.0f - s),   h11 = hn1 * (1.0f - s);
        float c10 = cn0 * (1.0f - s),   c11 = cn1 * (1.0f - s);

        *(float2*)&g_c1[idx] = make_float2(c10, c11);
        *(float2*)&g_h1f[wb][idx] = make_float2(h10, h11);
        *(uint32_t*)&g_h1h[wb][idx] = pack_hi(h10, h11);
        *(uint32_t*)&g_h1l[wb][idx] = pack_lo(h10, h11);
        *(uint32_t*)&g_x2h[idx] = pack_hi(x20, x21);
        *(uint32_t*)&g_x2l[idx] = pack_lo(x20, x21);
    }
}

// ---------------- scan: gates2 mma-GEMM + LSTM2 (+ fused gate t+1) ----------
__global__ void k_lstm2(int t, int rb, float* __restrict__ out2) {
    if (blockIdx.x >= H_ / 8) {
        // fused boundary gate for step t+1 (fp32 path)
        if (t + 1 >= T_) return;
        int b = (blockIdx.x - H_ / 8) * 8 + (threadIdx.x >> 5);
        int lane = threadIdx.x & 31;
        const float* h1 = g_h1f[rb ^ 1] + (size_t)b * H_;
        float u = 0.f;
        for (int h = lane; h < H_; h += 32) u += h1[h] * g_wshv[h];
#pragma unroll
        for (int o = 16; o > 0; o >>= 1) u += __shfl_xor_sync(0xffffffffu, u, o);
        if (lane == 0) {
            u += g_abd[b * T_ + t + 1];
            float z = 1.0f / (1.0f + expf(-u));
            g_s[b] = rintf(z);
        }
        return;
    }

    __shared__ __align__(16) bf16 As_h[128][PAD], As_l[128][PAD];
    __shared__ __align__(16) bf16 Bs_h[32][PAD],  Bs_l[32][PAD];

    int tid = threadIdx.x, lane = tid & 31, wid = tid >> 5;
    int gr = lane >> 2, tc = lane & 3;
    int hb = blockIdx.x * 8;

    float acc[4][4];
#pragma unroll
    for (int g = 0; g < 4; g++)
#pragma unroll
        for (int c = 0; c < 4; c++) acc[g][c] = 0.f;

    for (int k0 = 0; k0 < 2 * H_; k0 += 32) {
        bool first = (k0 < H_);
        const uint4* A4h = first ? (const uint4*)g_x2h : (const uint4*)g_h2h[rb];
        const uint4* A4l = first ? (const uint4*)g_x2l : (const uint4*)g_h2l[rb];
        const uint4* W4h = first ? (const uint4*)g_Wih2_h : (const uint4*)g_Whh2_h;
        const uint4* W4l = first ? (const uint4*)g_Wih2_l : (const uint4*)g_Whh2_l;
        int kq = (k0 & (H_ - 1)) >> 3;
#pragma unroll
        for (int rep = 0; rep < 2; rep++) {
            int u = tid + 256 * rep;
            int r = u >> 2, q = u & 3;
            *(uint4*)&As_h[r][q * 8] = A4h[r * 128 + kq + q];
            *(uint4*)&As_l[r][q * 8] = A4l[r * 128 + kq + q];
        }
        if (tid < 128) {
            int r = tid >> 2, q = tid & 3;
            int wr = (r >> 3) * H_ + hb + (r & 7);
            *(uint4*)&Bs_h[r][q * 8] = W4h[(size_t)wr * 128 + kq + q];
        } else {
            int u = tid - 128;
            int r = u >> 2, q = u & 3;
            int wr = (r >> 3) * H_ + hb + (r & 7);
            *(uint4*)&Bs_l[r][q * 8] = W4l[(size_t)wr * 128 + kq + q];
        }
        __syncthreads();
#pragma unroll
        for (int ks = 0; ks < 32; ks += 16) {
            int r0 = wid * 16 + gr;
            uint32_t ah0 = ld_s32(&As_h[r0][ks + 2 * tc]);
            uint32_t ah1 = ld_s32(&As_h[r0 + 8][ks + 2 * tc]);
            uint32_t ah2 = ld_s32(&As_h[r0][ks + 2 * tc + 8]);
            uint32_t ah3 = ld_s32(&As_h[r0 + 8][ks + 2 * tc + 8]);
            uint32_t al0 = ld_s32(&As_l[r0][ks + 2 * tc]);
            uint32_t al1 = ld_s32(&As_l[r0 + 8][ks + 2 * tc]);
            uint32_t al2 = ld_s32(&As_l[r0][ks + 2 * tc + 8]);
            uint32_t al3 = ld_s32(&As_l[r0 + 8][ks + 2 * tc + 8]);
#pragma unroll
            for (int g = 0; g < 4; g++) {
                int n0 = g * 8 + gr;
                uint32_t bh0 = ld_s32(&Bs_h[n0][ks + 2 * tc]);
                uint32_t bh1 = ld_s32(&Bs_h[n0][ks + 2 * tc + 8]);
                uint32_t bl0 = ld_s32(&Bs_l[n0][ks + 2 * tc]);
                uint32_t bl1 = ld_s32(&Bs_l[n0][ks + 2 * tc + 8]);
                float* d = acc[g];
                mma16816(d[0], d[1], d[2], d[3], ah0, ah1, ah2, ah3, bh0, bh1);
                mma16816(d[0], d[1], d[2], d[3], ah0, ah1, ah2, ah3, bl0, bl1);
                mma16816(d[0], d[1], d[2], d[3], al0, al1, al2, al3, bh0, bh1);
            }
        }
        __syncthreads();
    }

    int wb = rb ^ 1;
    int h0 = hb + 2 * tc;
#pragma unroll
    for (int rs = 0; rs < 2; rs++) {
        int b = wid * 16 + gr + 8 * rs;
        int idx = b * H_ + h0;
        float2 coldp = *(const float2*)&g_c2[idx];

        float gi0 = acc[0][2 * rs], gi1 = acc[0][2 * rs + 1];
        float gf0 = acc[1][2 * rs], gf1 = acc[1][2 * rs + 1];
        float gg0 = acc[2][2 * rs], gg1 = acc[2][2 * rs + 1];
        float go0 = acc[3][2 * rs], go1 = acc[3][2 * rs + 1];

        float cn0 = sigf(gf0) * coldp.x + sigf(gi0) * tanhf(gg0);
        float cn1 = sigf(gf1) * coldp.y + sigf(gi1) * tanhf(gg1);
        float hn0 = sigf(go0) * tanhf(cn0);
        float hn1 = sigf(go1) * tanhf(cn1);

        *(float2*)&g_c2[idx] = make_float2(cn0, cn1);
        *(uint32_t*)&g_h2h[wb][idx] = pack_hi(hn0, hn1);
        *(uint32_t*)&g_h2l[wb][idx] = pack_lo(hn0, hn1);
        if (out2) *(float2*)&out2[idx] = make_float2(hn0, hn1);
    }
}

// ---------------- launch ---------------------------------------------------
extern "C" void kernel_launch(void* const* d_in, const int* in_sizes, int n_in,
                              void* d_out, int out_size) {
    const float* video   = (const float*)d_in[0];
    const float* W_embed = (const float*)d_in[1];
    const float* b_embed = (const float*)d_in[2];
    const float* W_ih1   = (const float*)d_in[3];
    const float* W_hh1   = (const float*)d_in[4];
    const float* b1      = (const float*)d_in[5];
    const float* Wsi     = (const float*)d_in[6];
    const float* Wsh     = (const float*)d_in[7];
    const float* b_bd    = (const float*)d_in[8];
    const float* vs      = (const float*)d_in[9];
    const float* W_ih2   = (const float*)d_in[10];
    const float* W_hh2   = (const float*)d_in[11];
    float* out = (float*)d_out;

    bf16 *vidh, *vidl, *Vh, *Vl, *Weh, *Wel, *W1h, *W1l;
    float *pV, *pA1;
    cudaGetSymbolAddress((void**)&vidh, g_vidh);  cudaGetSymbolAddress((void**)&vidl, g_vidl);
    cudaGetSymbolAddress((void**)&Vh, g_Vh);      cudaGetSymbolAddress((void**)&Vl, g_Vl);
    cudaGetSymbolAddress((void**)&Weh, g_Wemb_h); cudaGetSymbolAddress((void**)&Wel, g_Wemb_l);
    cudaGetSymbolAddress((void**)&W1h, g_Wih1_h); cudaGetSymbolAddress((void**)&W1l, g_Wih1_l);
    cudaGetSymbolAddress((void**)&pV, g_V);       cudaGetSymbolAddress((void**)&pA1, g_A1);
    bf16 *Wh1h, *Wh1l, *Wi2h, *Wi2l, *Wh2h, *Wh2l;
    cudaGetSymbolAddress((void**)&Wh1h, g_Whh1_h); cudaGetSymbolAddress((void**)&Wh1l, g_Whh1_l);
    cudaGetSymbolAddress((void**)&Wi2h, g_Wih2_h); cudaGetSymbolAddress((void**)&Wi2l, g_Wih2_l);
    cudaGetSymbolAddress((void**)&Wh2h, g_Whh2_h); cudaGetSymbolAddress((void**)&Wh2l, g_Whh2_l);

    // boundary-detector projections (fp32 path)
    k_proj<<<9, 128>>>(Wsi, Wsh, b_bd, vs);

    // split fp32 operands into (hi, lo) bf16 pairs
    auto splitN = [&](const float* src, bf16* h, bf16* l, int n) {
        int n4 = n / 4;
        k_split4<<<(n4 + 255) / 256, 256>>>(src, h, l, n4);
    };
    splitN(video,  vidh, vidl, B_ * T_ * F_);
    splitN(W_embed, Weh, Wel, H_ * F_);
    splitN(W_ih1,  W1h, W1l, G4_ * H_);
    splitN(W_hh1,  Wh1h, Wh1l, G4_ * H_);
    splitN(W_ih2,  Wi2h, Wi2l, G4_ * H_);
    splitN(W_hh2,  Wh2h, Wh2l, G4_ * H_);

    // embed: V = relu(video @ W_embed^T + b_embed), also emit split-bf16 V
    mm_pre<true, true, true><<<dim3(H_ / 64, (B_ * T_) / 128), 256>>>(
        vidh, vidl, Weh, Wel, b_embed, pV, Vh, Vl, H_, F_);

    // A1 = V @ W_ih1^T + b1
    mm_pre<false, true, false><<<dim3(G4_ / 64, (B_ * T_) / 128), 256>>>(
        Vh, Vl, W1h, W1l, b1, pA1, nullptr, nullptr, G4_, H_);

    // abd + state init
    k_abd<<<(B_ * T_) / 8, 256>>>();
    k_init<<<(B_ * H_ + 255) / 256, 256>>>();

    // sequential scan
    for (int t = 0; t < T_; t++) {
        int rb = t & 1;
        k_lstm1<<<H_ / 8, 256>>>(t, rb);
        k_lstm2<<<H_ / 8 + B_ / 8, 256>>>(t, rb, (t == T_ - 1) ? out : nullptr);
    }
}

// round 9
// speedup vs baseline: 3.6606x; 1.6972x over previous
#include <cuda_runtime.h>
#include <cuda_bf16.h>
#include <stdint.h>
#include <math.h>

#define B_ 128
#define T_ 64
#define F_ 2048
#define H_ 1024
#define M_ 512
#define G4_ 4096
#define PAD 40

typedef __nv_bfloat16 bf16;

// ---------------- fp32 scratch ---------------------------------------------
__device__ float g_V[B_ * T_ * H_];
__device__ float g_A1[(size_t)B_ * T_ * G4_];
__device__ float g_abd[B_ * T_];
__device__ float g_wsiv[H_], g_wshv[H_];
__device__ float g_bb;
__device__ float g_h1f[2][B_ * H_];
__device__ float g_c1[B_ * H_], g_c2[B_ * H_];
__device__ float g_s[B_];

// ---------------- split-bf16 operands --------------------------------------
__device__ bf16 g_vidh[B_ * T_ * F_], g_vidl[B_ * T_ * F_];
__device__ bf16 g_Vh[B_ * T_ * H_],   g_Vl[B_ * T_ * H_];
__device__ bf16 g_Wemb_h[H_ * F_],    g_Wemb_l[H_ * F_];
__device__ bf16 g_Wih1_h[G4_ * H_],   g_Wih1_l[G4_ * H_];
__device__ bf16 g_Whh1_h[G4_ * H_],   g_Whh1_l[G4_ * H_];
__device__ bf16 g_Wih2_h[G4_ * H_],   g_Wih2_l[G4_ * H_];
__device__ bf16 g_Whh2_h[G4_ * H_],   g_Whh2_l[G4_ * H_];
__device__ bf16 g_h1h[2][B_ * H_],    g_h1l[2][B_ * H_];
__device__ bf16 g_h2h[2][B_ * H_],    g_h2l[2][B_ * H_];
__device__ bf16 g_x2h[B_ * H_],       g_x2l[B_ * H_];

__device__ __forceinline__ float sigf(float x) { return 1.0f / (1.0f + expf(-x)); }
__device__ __forceinline__ uint32_t pack_hi(float x, float y) {
    __nv_bfloat162 t; t.x = __float2bfloat16(x); t.y = __float2bfloat16(y);
    return *(uint32_t*)&t;
}
__device__ __forceinline__ uint32_t pack_lo(float x, float y) {
    bf16 hx = __float2bfloat16(x), hy = __float2bfloat16(y);
    __nv_bfloat162 t;
    t.x = __float2bfloat16(x - __bfloat162float(hx));
    t.y = __float2bfloat16(y - __bfloat162float(hy));
    return *(uint32_t*)&t;
}
__device__ __forceinline__ void mma16816(float& c0, float& c1, float& c2, float& c3,
                                         uint32_t a0, uint32_t a1, uint32_t a2, uint32_t a3,
                                         uint32_t b0, uint32_t b1) {
    asm volatile(
        "mma.sync.aligned.m16n8k16.row.col.f32.bf16.bf16.f32 "
        "{%0,%1,%2,%3},{%4,%5,%6,%7},{%8,%9},{%0,%1,%2,%3};"
        : "+f"(c0), "+f"(c1), "+f"(c2), "+f"(c3)
        : "r"(a0), "r"(a1), "r"(a2), "r"(a3), "r"(b0), "r"(b1));
}
__device__ __forceinline__ uint32_t ld_s32(const bf16* p) { return *(const uint32_t*)p; }
__device__ __forceinline__ uint32_t smem_to_u32(const void* p) {
    uint32_t a;
    asm("{ .reg .u64 t; cvta.to.shared.u64 t, %1; cvt.u32.u64 %0, t; }" : "=r"(a) : "l"(p));
    return a;
}
__device__ __forceinline__ void cpa16(uint32_t dst, const void* src) {
    asm volatile("cp.async.cg.shared.global [%0], [%1], 16;" :: "r"(dst), "l"(src));
}
#define CP_COMMIT() asm volatile("cp.async.commit_group;" ::: "memory")
#define CP_WAIT1()  asm volatile("cp.async.wait_group 1;" ::: "memory")
#define CP_WAIT0()  asm volatile("cp.async.wait_group 0;" ::: "memory")

// ---------------- fused split: all 6 fp32 tensors -> (hi,lo) bf16 -----------
// prefix boundaries (in float4 units)
#define SPLIT_TOTAL4 8912896
__global__ void k_split_all(const float* __restrict__ video, const float* __restrict__ W_embed,
                            const float* __restrict__ W_ih1, const float* __restrict__ W_hh1,
                            const float* __restrict__ W_ih2, const float* __restrict__ W_hh2) {
    long i = (long)blockIdx.x * 256 + threadIdx.x;
    const float* src; bf16 *h, *l; long j;
    if (i < 4194304L)       { src = video;   h = g_vidh;   l = g_vidl;   j = i; }
    else if (i < 4718592L)  { src = W_embed; h = g_Wemb_h; l = g_Wemb_l; j = i - 4194304L; }
    else if (i < 5767168L)  { src = W_ih1;   h = g_Wih1_h; l = g_Wih1_l; j = i - 4718592L; }
    else if (i < 6815744L)  { src = W_hh1;   h = g_Whh1_h; l = g_Whh1_l; j = i - 5767168L; }
    else if (i < 7864320L)  { src = W_ih2;   h = g_Wih2_h; l = g_Wih2_l; j = i - 6815744L; }
    else                    { src = W_hh2;   h = g_Whh2_h; l = g_Whh2_l; j = i - 7864320L; }
    float4 v = ((const float4*)src)[j];
    uint2 hp, lp;
    hp.x = pack_hi(v.x, v.y); hp.y = pack_hi(v.z, v.w);
    lp.x = pack_lo(v.x, v.y); lp.y = pack_lo(v.z, v.w);
    ((uint2*)h)[j] = hp;
    ((uint2*)l)[j] = lp;
}

// ---------------- boundary-detector projections ----------------------------
__global__ void k_proj(const float* __restrict__ Wsi, const float* __restrict__ Wsh,
                       const float* __restrict__ b_bd, const float* __restrict__ vs) {
    int blk = blockIdx.x;
    if (blk < 8) {
        int h = blk * 128 + threadIdx.x;
        float s1 = 0.f, s2 = 0.f;
        for (int m = 0; m < M_; m++) {
            float v = vs[m];
            s1 += Wsi[m * H_ + h] * v;
            s2 += Wsh[m * H_ + h] * v;
        }
        g_wsiv[h] = s1;
        g_wshv[h] = s2;
    } else {
        __shared__ float red[128];
        float s = 0.f;
        for (int m = threadIdx.x; m < M_; m += 128) s += b_bd[m] * vs[m];
        red[threadIdx.x] = s;
        __syncthreads();
        for (int st = 64; st > 0; st >>= 1) {
            if (threadIdx.x < st) red[threadIdx.x] += red[threadIdx.x + st];
            __syncthreads();
        }
        if (threadIdx.x == 0) g_bb = red[0];
    }
}

// ---------------- precompute GEMM (HMMA split-bf16, known good) -------------
template <bool RELU, bool BIAS, bool SPLIT>
__global__ void mm_pre(const bf16* __restrict__ Ah, const bf16* __restrict__ Al,
                       const bf16* __restrict__ Bh, const bf16* __restrict__ Bl,
                       const float* __restrict__ bias, float* __restrict__ C,
                       bf16* __restrict__ Ch, bf16* __restrict__ Cl, int N, int K) {
    __shared__ __align__(16) bf16 As_h[128][PAD], As_l[128][PAD];
    __shared__ __align__(16) bf16 Bs_h[64][PAD],  Bs_l[64][PAD];

    int tid = threadIdx.x, lane = tid & 31, wid = tid >> 5;
    int wm = wid >> 2, wn = wid & 3;
    int gr = lane >> 2, tc = lane & 3;
    int bn0 = blockIdx.x * 64, bm0 = blockIdx.y * 128;
    int K8 = K >> 3;
    const uint4* A4h = (const uint4*)Ah; const uint4* A4l = (const uint4*)Al;
    const uint4* B4h = (const uint4*)Bh; const uint4* B4l = (const uint4*)Bl;

    float acc[4][2][4];
#pragma unroll
    for (int a = 0; a < 4; a++)
#pragma unroll
        for (int b = 0; b < 2; b++)
#pragma unroll
            for (int c = 0; c < 4; c++) acc[a][b][c] = 0.f;

    for (int k0 = 0; k0 < K; k0 += 32) {
        int kq = k0 >> 3;
#pragma unroll
        for (int rep = 0; rep < 2; rep++) {
            int u = tid + 256 * rep;
            int r = u >> 2, q = u & 3;
            *(uint4*)&As_h[r][q * 8] = A4h[(size_t)(bm0 + r) * K8 + kq + q];
            *(uint4*)&As_l[r][q * 8] = A4l[(size_t)(bm0 + r) * K8 + kq + q];
        }
        {
            int r = tid >> 2, q = tid & 3;
            *(uint4*)&Bs_h[r][q * 8] = B4h[(size_t)(bn0 + r) * K8 + kq + q];
            *(uint4*)&Bs_l[r][q * 8] = B4l[(size_t)(bn0 + r) * K8 + kq + q];
        }
        __syncthreads();
#pragma unroll
        for (int ks = 0; ks < 32; ks += 16) {
            uint32_t afh[4][4], afl[4][4];
#pragma unroll
            for (int mt = 0; mt < 4; mt++) {
                int r0 = wm * 64 + mt * 16 + gr;
                afh[mt][0] = ld_s32(&As_h[r0][ks + 2 * tc]);
                afh[mt][1] = ld_s32(&As_h[r0 + 8][ks + 2 * tc]);
                afh[mt][2] = ld_s32(&As_h[r0][ks + 2 * tc + 8]);
                afh[mt][3] = ld_s32(&As_h[r0 + 8][ks + 2 * tc + 8]);
                afl[mt][0] = ld_s32(&As_l[r0][ks + 2 * tc]);
                afl[mt][1] = ld_s32(&As_l[r0 + 8][ks + 2 * tc]);
                afl[mt][2] = ld_s32(&As_l[r0][ks + 2 * tc + 8]);
                afl[mt][3] = ld_s32(&As_l[r0 + 8][ks + 2 * tc + 8]);
            }
#pragma unroll
            for (int nt = 0; nt < 2; nt++) {
                int n0 = wn * 16 + nt * 8 + gr;
                uint32_t bh0 = ld_s32(&Bs_h[n0][ks + 2 * tc]);
                uint32_t bh1 = ld_s32(&Bs_h[n0][ks + 2 * tc + 8]);
                uint32_t bl0 = ld_s32(&Bs_l[n0][ks + 2 * tc]);
                uint32_t bl1 = ld_s32(&Bs_l[n0][ks + 2 * tc + 8]);
#pragma unroll
                for (int mt = 0; mt < 4; mt++) {
                    float* d = acc[mt][nt];
                    mma16816(d[0], d[1], d[2], d[3], afh[mt][0], afh[mt][1], afh[mt][2], afh[mt][3], bh0, bh1);
                    mma16816(d[0], d[1], d[2], d[3], afh[mt][0], afh[mt][1], afh[mt][2], afh[mt][3], bl0, bl1);
                    mma16816(d[0], d[1], d[2], d[3], afl[mt][0], afl[mt][1], afl[mt][2], afl[mt][3], bh0, bh1);
                }
            }
        }
        __syncthreads();
    }

#pragma unroll
    for (int mt = 0; mt < 4; mt++)
#pragma unroll
        for (int nt = 0; nt < 2; nt++) {
            int row0 = bm0 + wm * 64 + mt * 16 + gr;
            int col = bn0 + wn * 16 + nt * 8 + 2 * tc;
            float2 bs = BIAS ? *(const float2*)&bias[col] : make_float2(0.f, 0.f);
#pragma unroll
            for (int rs = 0; rs < 2; rs++) {
                int row = row0 + 8 * rs;
                float v0 = acc[mt][nt][2 * rs] + bs.x;
                float v1 = acc[mt][nt][2 * rs + 1] + bs.y;
                if (RELU) { v0 = fmaxf(v0, 0.f); v1 = fmaxf(v1, 0.f); }
                *(float2*)&C[(size_t)row * N + col] = make_float2(v0, v1);
                if (SPLIT) {
                    *(uint32_t*)&Ch[(size_t)row * N + col] = pack_hi(v0, v1);
                    *(uint32_t*)&Cl[(size_t)row * N + col] = pack_lo(v0, v1);
                }
            }
        }
}

// ---------------- fused abd + t0-gate + state init -------------------------
// blocks [0,1024): abd rows (8 rows/block); blocks [1024,1536): zero state
__global__ void k_abd_init() {
    if (blockIdx.x < 1024) {
        int r = blockIdx.x * 8 + (threadIdx.x >> 5);
        int lane = threadIdx.x & 31;
        const float* vr = g_V + (size_t)r * H_;
        float s = 0.f;
        for (int h = lane; h < H_; h += 32) s += vr[h] * g_wsiv[h];
#pragma unroll
        for (int o = 16; o > 0; o >>= 1) s += __shfl_xor_sync(0xffffffffu, s, o);
        if (lane == 0) {
            float u = s + g_bb;
            g_abd[r] = u;
            if ((r & (T_ - 1)) == 0)   // t = 0: h1 = 0 -> gate directly
                g_s[r >> 6] = rintf(sigf(u));
        }
    } else {
        int i = (blockIdx.x - 1024) * 256 + threadIdx.x;
        if (i < B_ * H_) {
            g_c1[i] = 0.f; g_c2[i] = 0.f;
            bf16 z = __float2bfloat16(0.f);
            g_h1h[0][i] = z; g_h1l[0][i] = z;
            g_h2h[0][i] = z; g_h2l[0][i] = z;
        }
    }
}

// ================= cp.async pipelined scan kernels ==========================
// BK=64. smem per buffer: Ah(128x72) Al Bh(32x72) Bl; two buffers.
#define A_ST   72
#define A_TILE (128 * A_ST * 2)                  // 18432 B
#define B_TILE (32 * A_ST * 2)                   // 4608 B
#define BUF_SZ (2 * A_TILE + 2 * B_TILE)         // 46080 B
#define SM_AH(b) ((b) * BUF_SZ)
#define SM_AL(b) ((b) * BUF_SZ + A_TILE)
#define SM_BH(b) ((b) * BUF_SZ + 2 * A_TILE)
#define SM_BL(b) ((b) * BUF_SZ + 2 * A_TILE + B_TILE)
#define SMEM_SCAN (2 * BUF_SZ)                   // 92160 B

// prefetch A tile: 128 rows x 64 bf16 hi+lo; kq = k-offset in 16B units
__device__ __forceinline__ void pf_A(uint32_t sb, int buf,
                                     const uint4* __restrict__ Ah4,
                                     const uint4* __restrict__ Al4,
                                     int kq, int tid) {
#pragma unroll
    for (int rep = 0; rep < 4; rep++) {
        int u = tid + 256 * rep;
        int r = u >> 3, q = u & 7;
        uint32_t off = (uint32_t)(r * (A_ST * 2) + q * 16);
        cpa16(sb + SM_AH(buf) + off, Ah4 + (size_t)r * 128 + kq + q);
        cpa16(sb + SM_AL(buf) + off, Al4 + (size_t)r * 128 + kq + q);
    }
}
// prefetch B tile: 32 rows (4 gates x 8 cols) x 64 bf16 hi+lo
__device__ __forceinline__ void pf_B(uint32_t sb, int buf,
                                     const uint4* __restrict__ Wh4,
                                     const uint4* __restrict__ Wl4,
                                     int hb, int kq, int tid) {
    int n = tid >> 3, q = tid & 7;               // n 0..31
    int wr = (n >> 3) * H_ + hb + (n & 7);
    uint32_t off = (uint32_t)(n * (A_ST * 2) + q * 16);
    cpa16(sb + SM_BH(buf) + off, Wh4 + (size_t)wr * 128 + kq + q);
    cpa16(sb + SM_BL(buf) + off, Wl4 + (size_t)wr * 128 + kq + q);
}
// one BK=64 chunk of 3-term split MMAs; warp owns m16 rows [wid*16, +16)
__device__ __forceinline__ void comp_chunk(const char* smem, int buf, int wid, int lane,
                                           float acc[4][4]) {
    int gr = lane >> 2, tc = lane & 3;
    const bf16* Ah = (const bf16*)(smem + SM_AH(buf));
    const bf16* Al = (const bf16*)(smem + SM_AL(buf));
    const bf16* Bh = (const bf16*)(smem + SM_BH(buf));
    const bf16* Bl = (const bf16*)(smem + SM_BL(buf));
    int r0 = wid * 16 + gr;
#pragma unroll
    for (int ks = 0; ks < 64; ks += 16) {
        int c0 = ks + 2 * tc;
        uint32_t ah0 = ld_s32(&Ah[r0 * A_ST + c0]);
        uint32_t ah1 = ld_s32(&Ah[(r0 + 8) * A_ST + c0]);
        uint32_t ah2 = ld_s32(&Ah[r0 * A_ST + c0 + 8]);
        uint32_t ah3 = ld_s32(&Ah[(r0 + 8) * A_ST + c0 + 8]);
        uint32_t al0 = ld_s32(&Al[r0 * A_ST + c0]);
        uint32_t al1 = ld_s32(&Al[(r0 + 8) * A_ST + c0]);
        uint32_t al2 = ld_s32(&Al[r0 * A_ST + c0 + 8]);
        uint32_t al3 = ld_s32(&Al[(r0 + 8) * A_ST + c0 + 8]);
#pragma unroll
        for (int g = 0; g < 4; g++) {
            int n0 = g * 8 + gr;
            uint32_t bh0 = ld_s32(&Bh[n0 * A_ST + c0]);
            uint32_t bh1 = ld_s32(&Bh[n0 * A_ST + c0 + 8]);
            uint32_t bl0 = ld_s32(&Bl[n0 * A_ST + c0]);
            uint32_t bl1 = ld_s32(&Bl[n0 * A_ST + c0 + 8]);
            float* d = acc[g];
            mma16816(d[0], d[1], d[2], d[3], ah0, ah1, ah2, ah3, bh0, bh1);
            mma16816(d[0], d[1], d[2], d[3], ah0, ah1, ah2, ah3, bl0, bl1);
            mma16816(d[0], d[1], d[2], d[3], al0, al1, al2, al3, bh0, bh1);
        }
    }
}

// scan step 1: gates1 = h1 @ Whh1^T + A1 -> LSTM1 + boundary mask.
// grid = 128 CTAs (8 hidden cols each), 256 thr.
__global__ void __launch_bounds__(256) k_lstm1(int t, int rb) {
    extern __shared__ char smem[];
    uint32_t sb = smem_to_u32(smem);
    int tid = threadIdx.x, lane = tid & 31, wid = tid >> 5;
    int hb = blockIdx.x * 8;
    const uint4* Ah4 = (const uint4*)g_h1h[rb];
    const uint4* Al4 = (const uint4*)g_h1l[rb];
    const uint4* Wh4 = (const uint4*)g_Whh1_h;
    const uint4* Wl4 = (const uint4*)g_Whh1_l;

    float acc[4][4];
#pragma unroll
    for (int g = 0; g < 4; g++)
#pragma unroll
        for (int c = 0; c < 4; c++) acc[g][c] = 0.f;

    pf_A(sb, 0, Ah4, Al4, 0, tid);
    pf_B(sb, 0, Wh4, Wl4, hb, 0, tid);
    CP_COMMIT();
    for (int c = 0; c < 16; c++) {
        int buf = c & 1;
        if (c + 1 < 16) {
            pf_A(sb, buf ^ 1, Ah4, Al4, (c + 1) * 8, tid);
            pf_B(sb, buf ^ 1, Wh4, Wl4, hb, (c + 1) * 8, tid);
            CP_COMMIT();
            CP_WAIT1();
        } else {
            CP_WAIT0();
        }
        __syncthreads();
        comp_chunk(smem, buf, wid, lane, acc);
        __syncthreads();
    }

    // epilogue: LSTM1 pointwise + boundary mask
    int wb = rb ^ 1;
    int gr = lane >> 2, tc = lane & 3;
    int h0 = hb + 2 * tc;
#pragma unroll
    for (int rs = 0; rs < 2; rs++) {
        int b = wid * 16 + gr + 8 * rs;
        float s = g_s[b];
        const float* a1 = g_A1 + (size_t)(b * T_ + t) * G4_;
        float2 ai = *(const float2*)&a1[h0];
        float2 af = *(const float2*)&a1[1024 + h0];
        float2 ag = *(const float2*)&a1[2048 + h0];
        float2 ao = *(const float2*)&a1[3072 + h0];
        int idx = b * H_ + h0;
        float2 coldp = *(const float2*)&g_c1[idx];

        float gi0 = acc[0][2 * rs] + ai.x, gi1 = acc[0][2 * rs + 1] + ai.y;
        float gf0 = acc[1][2 * rs] + af.x, gf1 = acc[1][2 * rs + 1] + af.y;
        float gg0 = acc[2][2 * rs] + ag.x, gg1 = acc[2][2 * rs + 1] + ag.y;
        float go0 = acc[3][2 * rs] + ao.x, go1 = acc[3][2 * rs + 1] + ao.y;

        float cn0 = sigf(gf0) * coldp.x + sigf(gi0) * tanhf(gg0);
        float cn1 = sigf(gf1) * coldp.y + sigf(gi1) * tanhf(gg1);
        float hn0 = sigf(go0) * tanhf(cn0);
        float hn1 = sigf(go1) * tanhf(cn1);

        float x20 = hn0 * s,          x21 = hn1 * s;
        float h10 = hn0 * (1.0f - s), h11 = hn1 * (1.0f - s);
        float c10 = cn0 * (1.0f - s), c11 = cn1 * (1.0f - s);

        *(float2*)&g_c1[idx] = make_float2(c10, c11);
        *(float2*)&g_h1f[wb][idx] = make_float2(h10, h11);
        *(uint32_t*)&g_h1h[wb][idx] = pack_hi(h10, h11);
        *(uint32_t*)&g_h1l[wb][idx] = pack_lo(h10, h11);
        *(uint32_t*)&g_x2h[idx] = pack_hi(x20, x21);
        *(uint32_t*)&g_x2l[idx] = pack_lo(x20, x21);
    }
}

// scan step 2: gates2 = x2 @ Wih2^T + h2 @ Whh2^T (K=2048) -> LSTM2.
// grid = 144: [0,128) GEMM+LSTM2; [128,144) boundary gate for t+1 (fp32).
__global__ void __launch_bounds__(256) k_lstm2(int t, int rb, float* __restrict__ out2) {
    if (blockIdx.x >= 128) {
        if (t + 1 >= T_) return;
        int b = (blockIdx.x - 128) * 8 + (threadIdx.x >> 5);
        int lane = threadIdx.x & 31;
        const float* h1 = g_h1f[rb ^ 1] + (size_t)b * H_;
        float u = 0.f;
        for (int h = lane; h < H_; h += 32) u += h1[h] * g_wshv[h];
#pragma unroll
        for (int o = 16; o > 0; o >>= 1) u += __shfl_xor_sync(0xffffffffu, u, o);
        if (lane == 0) {
            u += g_abd[b * T_ + t + 1];
            g_s[b] = rintf(sigf(u));
        }
        return;
    }

    extern __shared__ char smem[];
    uint32_t sb = smem_to_u32(smem);
    int tid = threadIdx.x, lane = tid & 31, wid = tid >> 5;
    int hb = blockIdx.x * 8;

    float acc[4][4];
#pragma unroll
    for (int g = 0; g < 4; g++)
#pragma unroll
        for (int c = 0; c < 4; c++) acc[g][c] = 0.f;

    // chunk c: c<16 -> x2/Wih2, else h2/Whh2; kq = (c&15)*8
    auto pf_chunk = [&](int c, int buf) {
        bool first = (c < 16);
        const uint4* Ah4 = first ? (const uint4*)g_x2h : (const uint4*)g_h2h[rb];
        const uint4* Al4 = first ? (const uint4*)g_x2l : (const uint4*)g_h2l[rb];
        const uint4* Wh4 = first ? (const uint4*)g_Wih2_h : (const uint4*)g_Whh2_h;
        const uint4* Wl4 = first ? (const uint4*)g_Wih2_l : (const uint4*)g_Whh2_l;
        int kq = (c & 15) * 8;
        pf_A(sb, buf, Ah4, Al4, kq, tid);
        pf_B(sb, buf, Wh4, Wl4, hb, kq, tid);
    };

    pf_chunk(0, 0);
    CP_COMMIT();
    for (int c = 0; c < 32; c++) {
        int buf = c & 1;
        if (c + 1 < 32) {
            pf_chunk(c + 1, buf ^ 1);
            CP_COMMIT();
            CP_WAIT1();
        } else {
            CP_WAIT0();
        }
        __syncthreads();
        comp_chunk(smem, buf, wid, lane, acc);
        __syncthreads();
    }

    int wb = rb ^ 1;
    int gr = lane >> 2, tc = lane & 3;
    int h0 = hb + 2 * tc;
#pragma unroll
    for (int rs = 0; rs < 2; rs++) {
        int b = wid * 16 + gr + 8 * rs;
        int idx = b * H_ + h0;
        float2 coldp = *(const float2*)&g_c2[idx];

        float gi0 = acc[0][2 * rs], gi1 = acc[0][2 * rs + 1];
        float gf0 = acc[1][2 * rs], gf1 = acc[1][2 * rs + 1];
        float gg0 = acc[2][2 * rs], gg1 = acc[2][2 * rs + 1];
        float go0 = acc[3][2 * rs], go1 = acc[3][2 * rs + 1];

        float cn0 = sigf(gf0) * coldp.x + sigf(gi0) * tanhf(gg0);
        float cn1 = sigf(gf1) * coldp.y + sigf(gi1) * tanhf(gg1);
        float hn0 = sigf(go0) * tanhf(cn0);
        float hn1 = sigf(go1) * tanhf(cn1);

        *(float2*)&g_c2[idx] = make_float2(cn0, cn1);
        *(uint32_t*)&g_h2h[wb][idx] = pack_hi(hn0, hn1);
        *(uint32_t*)&g_h2l[wb][idx] = pack_lo(hn0, hn1);
        if (out2) *(float2*)&out2[idx] = make_float2(hn0, hn1);
    }
}

// ---------------- launch ---------------------------------------------------
extern "C" void kernel_launch(void* const* d_in, const int* in_sizes, int n_in,
                              void* d_out, int out_size) {
    const float* video   = (const float*)d_in[0];
    const float* W_embed = (const float*)d_in[1];
    const float* b_embed = (const float*)d_in[2];
    const float* W_ih1   = (const float*)d_in[3];
    const float* W_hh1   = (const float*)d_in[4];
    const float* b1      = (const float*)d_in[5];
    const float* Wsi     = (const float*)d_in[6];
    const float* Wsh     = (const float*)d_in[7];
    const float* b_bd    = (const float*)d_in[8];
    const float* vs      = (const float*)d_in[9];
    const float* W_ih2   = (const float*)d_in[10];
    const float* W_hh2   = (const float*)d_in[11];
    float* out = (float*)d_out;

    bf16 *vidh, *vidl, *Vh, *Vl, *Weh, *Wel, *W1h, *W1l;
    float *pV, *pA1;
    cudaGetSymbolAddress((void**)&vidh, g_vidh);  cudaGetSymbolAddress((void**)&vidl, g_vidl);
    cudaGetSymbolAddress((void**)&Vh, g_Vh);      cudaGetSymbolAddress((void**)&Vl, g_Vl);
    cudaGetSymbolAddress((void**)&Weh, g_Wemb_h); cudaGetSymbolAddress((void**)&Wel, g_Wemb_l);
    cudaGetSymbolAddress((void**)&W1h, g_Wih1_h); cudaGetSymbolAddress((void**)&W1l, g_Wih1_l);
    cudaGetSymbolAddress((void**)&pV, g_V);       cudaGetSymbolAddress((void**)&pA1, g_A1);

    cudaFuncSetAttribute(k_lstm1, cudaFuncAttributeMaxDynamicSharedMemorySize, SMEM_SCAN);
    cudaFuncSetAttribute(k_lstm2, cudaFuncAttributeMaxDynamicSharedMemorySize, SMEM_SCAN);

    // 1) boundary-detector projections (fp32)
    k_proj<<<9, 128>>>(Wsi, Wsh, b_bd, vs);

    // 2) fused split of all fp32 operands into (hi, lo) bf16
    k_split_all<<<SPLIT_TOTAL4 / 256, 256>>>(video, W_embed, W_ih1, W_hh1, W_ih2, W_hh2);

    // 3) embed: V = relu(video @ W_embed^T + b), also emit split-bf16 V
    mm_pre<true, true, true><<<dim3(H_ / 64, (B_ * T_) / 128), 256>>>(
        vidh, vidl, Weh, Wel, b_embed, pV, Vh, Vl, H_, F_);

    // 4) A1 = V @ W_ih1^T + b1
    mm_pre<false, true, false><<<dim3(G4_ / 64, (B_ * T_) / 128), 256>>>(
        Vh, Vl, W1h, W1l, b1, pA1, nullptr, nullptr, G4_, H_);

    // 5) abd + t0 gate + zero state
    k_abd_init<<<1536, 256>>>();

    // 6+) sequential scan (cp.async pipelined HMMA)
    for (int t = 0; t < T_; t++) {
        int rb = t & 1;
        k_lstm1<<<128, 256, SMEM_SCAN>>>(t, rb);
        k_lstm2<<<144, 256, SMEM_SCAN>>>(t, rb, (t == T_ - 1) ? out : nullptr);
    }
}

// round 10
// speedup vs baseline: 3.8863x; 1.0617x over previous
#include <cuda_runtime.h>
#include <cuda_bf16.h>
#include <stdint.h>
#include <math.h>

#define B_ 128
#define T_ 64
#define F_ 2048
#define H_ 1024
#define M_ 512
#define G4_ 4096
#define PAD 40

typedef __nv_bfloat16 bf16;

// ---------------- fp32 scratch ---------------------------------------------
__device__ float g_V[B_ * T_ * H_];
__device__ float g_A1[(size_t)B_ * T_ * G4_];
__device__ float g_abd[B_ * T_];
__device__ float g_wsiv[H_], g_wshv[H_];
__device__ float g_bb;
__device__ float g_h1f[2][B_ * H_];
__device__ float g_c1[B_ * H_], g_c2[B_ * H_];
__device__ float g_s[B_];

// ---------------- split-bf16 operands --------------------------------------
__device__ bf16 g_vidh[B_ * T_ * F_], g_vidl[B_ * T_ * F_];
__device__ bf16 g_Vh[B_ * T_ * H_],   g_Vl[B_ * T_ * H_];
__device__ bf16 g_Wemb_h[H_ * F_],    g_Wemb_l[H_ * F_];
__device__ bf16 g_Wih1_h[G4_ * H_],   g_Wih1_l[G4_ * H_];
__device__ bf16 g_Whh1_h[G4_ * H_],   g_Whh1_l[G4_ * H_];
__device__ bf16 g_Wih2_h[G4_ * H_],   g_Wih2_l[G4_ * H_];
__device__ bf16 g_Whh2_h[G4_ * H_],   g_Whh2_l[G4_ * H_];
__device__ bf16 g_h1h[2][B_ * H_],    g_h1l[2][B_ * H_];
__device__ bf16 g_h2h[2][B_ * H_],    g_h2l[2][B_ * H_];
__device__ bf16 g_x2h[B_ * H_],       g_x2l[B_ * H_];

__device__ __forceinline__ float sigf(float x) { return 1.0f / (1.0f + expf(-x)); }
__device__ __forceinline__ uint32_t pack_hi(float x, float y) {
    __nv_bfloat162 t; t.x = __float2bfloat16(x); t.y = __float2bfloat16(y);
    return *(uint32_t*)&t;
}
__device__ __forceinline__ uint32_t pack_lo(float x, float y) {
    bf16 hx = __float2bfloat16(x), hy = __float2bfloat16(y);
    __nv_bfloat162 t;
    t.x = __float2bfloat16(x - __bfloat162float(hx));
    t.y = __float2bfloat16(y - __bfloat162float(hy));
    return *(uint32_t*)&t;
}
__device__ __forceinline__ void mma16816(float& c0, float& c1, float& c2, float& c3,
                                         uint32_t a0, uint32_t a1, uint32_t a2, uint32_t a3,
                                         uint32_t b0, uint32_t b1) {
    asm volatile(
        "mma.sync.aligned.m16n8k16.row.col.f32.bf16.bf16.f32 "
        "{%0,%1,%2,%3},{%4,%5,%6,%7},{%8,%9},{%0,%1,%2,%3};"
        : "+f"(c0), "+f"(c1), "+f"(c2), "+f"(c3)
        : "r"(a0), "r"(a1), "r"(a2), "r"(a3), "r"(b0), "r"(b1));
}
__device__ __forceinline__ void ldsm_x4(uint32_t& r0, uint32_t& r1, uint32_t& r2, uint32_t& r3,
                                        uint32_t addr) {
    asm volatile("ldmatrix.sync.aligned.m8n8.x4.shared.b16 {%0,%1,%2,%3}, [%4];"
                 : "=r"(r0), "=r"(r1), "=r"(r2), "=r"(r3) : "r"(addr));
}
__device__ __forceinline__ uint32_t smem_to_u32(const void* p) {
    uint32_t a;
    asm("{ .reg .u64 t; cvta.to.shared.u64 t, %1; cvt.u32.u64 %0, t; }" : "=r"(a) : "l"(p));
    return a;
}
__device__ __forceinline__ void cpa16(uint32_t dst, const void* src) {
    asm volatile("cp.async.cg.shared.global [%0], [%1], 16;" :: "r"(dst), "l"(src));
}
#define CP_COMMIT() asm volatile("cp.async.commit_group;" ::: "memory")
#define CP_WAIT1()  asm volatile("cp.async.wait_group 1;" ::: "memory")
#define CP_WAIT0()  asm volatile("cp.async.wait_group 0;" ::: "memory")

// ---------------- fused split: all 6 fp32 tensors -> (hi,lo) bf16 -----------
#define SPLIT_TOTAL4 8912896
__global__ void k_split_all(const float* __restrict__ video, const float* __restrict__ W_embed,
                            const float* __restrict__ W_ih1, const float* __restrict__ W_hh1,
                            const float* __restrict__ W_ih2, const float* __restrict__ W_hh2) {
    long i = (long)blockIdx.x * 256 + threadIdx.x;
    const float* src; bf16 *h, *l; long j;
    if (i < 4194304L)       { src = video;   h = g_vidh;   l = g_vidl;   j = i; }
    else if (i < 4718592L)  { src = W_embed; h = g_Wemb_h; l = g_Wemb_l; j = i - 4194304L; }
    else if (i < 5767168L)  { src = W_ih1;   h = g_Wih1_h; l = g_Wih1_l; j = i - 4718592L; }
    else if (i < 6815744L)  { src = W_hh1;   h = g_Whh1_h; l = g_Whh1_l; j = i - 5767168L; }
    else if (i < 7864320L)  { src = W_ih2;   h = g_Wih2_h; l = g_Wih2_l; j = i - 6815744L; }
    else                    { src = W_hh2;   h = g_Whh2_h; l = g_Whh2_l; j = i - 7864320L; }
    float4 v = ((const float4*)src)[j];
    uint2 hp, lp;
    hp.x = pack_hi(v.x, v.y); hp.y = pack_hi(v.z, v.w);
    lp.x = pack_lo(v.x, v.y); lp.y = pack_lo(v.z, v.w);
    ((uint2*)h)[j] = hp;
    ((uint2*)l)[j] = lp;
}

// ---------------- boundary-detector projections ----------------------------
__global__ void k_proj(const float* __restrict__ Wsi, const float* __restrict__ Wsh,
                       const float* __restrict__ b_bd, const float* __restrict__ vs) {
    int blk = blockIdx.x;
    if (blk < 8) {
        int h = blk * 128 + threadIdx.x;
        float s1 = 0.f, s2 = 0.f;
        for (int m = 0; m < M_; m++) {
            float v = vs[m];
            s1 += Wsi[m * H_ + h] * v;
            s2 += Wsh[m * H_ + h] * v;
        }
        g_wsiv[h] = s1;
        g_wshv[h] = s2;
    } else {
        __shared__ float red[128];
        float s = 0.f;
        for (int m = threadIdx.x; m < M_; m += 128) s += b_bd[m] * vs[m];
        red[threadIdx.x] = s;
        __syncthreads();
        for (int st = 64; st > 0; st >>= 1) {
            if (threadIdx.x < st) red[threadIdx.x] += red[threadIdx.x + st];
            __syncthreads();
        }
        if (threadIdx.x == 0) g_bb = red[0];
    }
}

// ---------------- precompute GEMM (HMMA split-bf16 + ldmatrix) --------------
template <bool RELU, bool BIAS, bool SPLIT>
__global__ void mm_pre(const bf16* __restrict__ Ah, const bf16* __restrict__ Al,
                       const bf16* __restrict__ Bh, const bf16* __restrict__ Bl,
                       const float* __restrict__ bias, float* __restrict__ C,
                       bf16* __restrict__ Ch, bf16* __restrict__ Cl, int N, int K) {
    __shared__ __align__(16) bf16 As_h[128][PAD], As_l[128][PAD];
    __shared__ __align__(16) bf16 Bs_h[64][PAD],  Bs_l[64][PAD];

    int tid = threadIdx.x, lane = tid & 31, wid = tid >> 5;
    int wm = wid >> 2, wn = wid & 3;
    int gr = lane >> 2, tc = lane & 3;
    int bn0 = blockIdx.x * 64, bm0 = blockIdx.y * 128;
    int K8 = K >> 3;
    const uint4* A4h = (const uint4*)Ah; const uint4* A4l = (const uint4*)Al;
    const uint4* B4h = (const uint4*)Bh; const uint4* B4l = (const uint4*)Bl;

    uint32_t sAh = smem_to_u32(&As_h[0][0]), sAl = smem_to_u32(&As_l[0][0]);
    uint32_t sBh = smem_to_u32(&Bs_h[0][0]), sBl = smem_to_u32(&Bs_l[0][0]);
    // ldmatrix per-lane address offsets (bytes), stride = PAD*2 = 80
    uint32_t aOff = (uint32_t)((wm * 64 + (lane & 15)) * (PAD * 2) + (lane >> 4) * 16);
    uint32_t bOff = (uint32_t)((wn * 16 + ((lane >> 4) & 1) * 8 + (lane & 7)) * (PAD * 2)
                               + ((lane >> 3) & 1) * 16);

    float acc[4][2][4];
#pragma unroll
    for (int a = 0; a < 4; a++)
#pragma unroll
        for (int b = 0; b < 2; b++)
#pragma unroll
            for (int c = 0; c < 4; c++) acc[a][b][c] = 0.f;

    for (int k0 = 0; k0 < K; k0 += 32) {
        int kq = k0 >> 3;
#pragma unroll
        for (int rep = 0; rep < 2; rep++) {
            int u = tid + 256 * rep;
            int r = u >> 2, q = u & 3;
            *(uint4*)&As_h[r][q * 8] = A4h[(size_t)(bm0 + r) * K8 + kq + q];
            *(uint4*)&As_l[r][q * 8] = A4l[(size_t)(bm0 + r) * K8 + kq + q];
        }
        {
            int r = tid >> 2, q = tid & 3;
            *(uint4*)&Bs_h[r][q * 8] = B4h[(size_t)(bn0 + r) * K8 + kq + q];
            *(uint4*)&Bs_l[r][q * 8] = B4l[(size_t)(bn0 + r) * K8 + kq + q];
        }
        __syncthreads();
#pragma unroll
        for (int ks = 0; ks < 32; ks += 16) {
            uint32_t kb = (uint32_t)(ks * 2);
            uint32_t afh[4][4], afl[4][4], bh[4], bl[4];
#pragma unroll
            for (int mt = 0; mt < 4; mt++) {
                uint32_t ao = aOff + (uint32_t)(mt * 16 * (PAD * 2)) + kb;
                ldsm_x4(afh[mt][0], afh[mt][1], afh[mt][2], afh[mt][3], sAh + ao);
                ldsm_x4(afl[mt][0], afl[mt][1], afl[mt][2], afl[mt][3], sAl + ao);
            }
            ldsm_x4(bh[0], bh[1], bh[2], bh[3], sBh + bOff + kb);
            ldsm_x4(bl[0], bl[1], bl[2], bl[3], sBl + bOff + kb);
#pragma unroll
            for (int nt = 0; nt < 2; nt++) {
#pragma unroll
                for (int mt = 0; mt < 4; mt++) {
                    float* d = acc[mt][nt];
                    mma16816(d[0], d[1], d[2], d[3], afh[mt][0], afh[mt][1], afh[mt][2], afh[mt][3], bh[2 * nt], bh[2 * nt + 1]);
                    mma16816(d[0], d[1], d[2], d[3], afh[mt][0], afh[mt][1], afh[mt][2], afh[mt][3], bl[2 * nt], bl[2 * nt + 1]);
                    mma16816(d[0], d[1], d[2], d[3], afl[mt][0], afl[mt][1], afl[mt][2], afl[mt][3], bh[2 * nt], bh[2 * nt + 1]);
                }
            }
        }
        __syncthreads();
    }

#pragma unroll
    for (int mt = 0; mt < 4; mt++)
#pragma unroll
        for (int nt = 0; nt < 2; nt++) {
            int row0 = bm0 + wm * 64 + mt * 16 + gr;
            int col = bn0 + wn * 16 + nt * 8 + 2 * tc;
            float2 bs = BIAS ? *(const float2*)&bias[col] : make_float2(0.f, 0.f);
#pragma unroll
            for (int rs = 0; rs < 2; rs++) {
                int row = row0 + 8 * rs;
                float v0 = acc[mt][nt][2 * rs] + bs.x;
                float v1 = acc[mt][nt][2 * rs + 1] + bs.y;
                if (RELU) { v0 = fmaxf(v0, 0.f); v1 = fmaxf(v1, 0.f); }
                *(float2*)&C[(size_t)row * N + col] = make_float2(v0, v1);
                if (SPLIT) {
                    *(uint32_t*)&Ch[(size_t)row * N + col] = pack_hi(v0, v1);
                    *(uint32_t*)&Cl[(size_t)row * N + col] = pack_lo(v0, v1);
                }
            }
        }
}

// ---------------- fused abd + t0-gate + state init -------------------------
__global__ void k_abd_init() {
    if (blockIdx.x < 1024) {
        int r = blockIdx.x * 8 + (threadIdx.x >> 5);
        int lane = threadIdx.x & 31;
        const float* vr = g_V + (size_t)r * H_;
        float s = 0.f;
        for (int h = lane; h < H_; h += 32) s += vr[h] * g_wsiv[h];
#pragma unroll
        for (int o = 16; o > 0; o >>= 1) s += __shfl_xor_sync(0xffffffffu, s, o);
        if (lane == 0) {
            float u = s + g_bb;
            g_abd[r] = u;
            if ((r & (T_ - 1)) == 0)
                g_s[r >> 6] = rintf(sigf(u));
        }
    } else {
        int i = (blockIdx.x - 1024) * 256 + threadIdx.x;
        if (i < B_ * H_) {
            g_c1[i] = 0.f; g_c2[i] = 0.f;
            bf16 z = __float2bfloat16(0.f);
            g_h1h[0][i] = z; g_h1l[0][i] = z;
            g_h2h[0][i] = z; g_h2l[0][i] = z;
        }
    }
}

// ================= cp.async pipelined scan kernels (BK=128, ldmatrix) =======
#define A_ST   136                               // bf16 stride (272 B rows)
#define A_TILE (128 * A_ST * 2)                  // 34816 B
#define B_TILE (32 * A_ST * 2)                   // 8704 B
#define BUF_SZ (2 * A_TILE + 2 * B_TILE)         // 87040 B
#define SM_AH(b) ((b) * BUF_SZ)
#define SM_AL(b) ((b) * BUF_SZ + A_TILE)
#define SM_BH(b) ((b) * BUF_SZ + 2 * A_TILE)
#define SM_BL(b) ((b) * BUF_SZ + 2 * A_TILE + B_TILE)
#define SMEM_SCAN (2 * BUF_SZ)                   // 174080 B

// prefetch A tile: 128 rows x 128 bf16 hi+lo; kq = k-offset in 16B units
__device__ __forceinline__ void pf_A(uint32_t sb, int buf,
                                     const uint4* __restrict__ Ah4,
                                     const uint4* __restrict__ Al4,
                                     int kq, int tid) {
#pragma unroll
    for (int rep = 0; rep < 8; rep++) {
        int u = tid + 256 * rep;
        int r = u >> 4, q = u & 15;
        uint32_t off = (uint32_t)(r * (A_ST * 2) + q * 16);
        cpa16(sb + SM_AH(buf) + off, Ah4 + (size_t)r * 128 + kq + q);
        cpa16(sb + SM_AL(buf) + off, Al4 + (size_t)r * 128 + kq + q);
    }
}
// prefetch B tile: 32 rows (4 gates x 8 cols) x 128 bf16 hi+lo
__device__ __forceinline__ void pf_B(uint32_t sb, int buf,
                                     const uint4* __restrict__ Wh4,
                                     const uint4* __restrict__ Wl4,
                                     int hb, int kq, int tid) {
#pragma unroll
    for (int rep = 0; rep < 2; rep++) {
        int u = tid + 256 * rep;
        int n = u >> 4, q = u & 15;
        int wr = (n >> 3) * H_ + hb + (n & 7);
        uint32_t off = (uint32_t)(n * (A_ST * 2) + q * 16);
        cpa16(sb + SM_BH(buf) + off, Wh4 + (size_t)wr * 128 + kq + q);
        cpa16(sb + SM_BL(buf) + off, Wl4 + (size_t)wr * 128 + kq + q);
    }
}
// one BK=128 chunk: 8 k16-steps x (6 LDSM + 12 MMA); warp owns m16 rows wid*16..+15
__device__ __forceinline__ void comp_chunk(uint32_t sb, int buf, int wid, int lane,
                                           float acc[4][4]) {
    uint32_t aOff = (uint32_t)((wid * 16 + (lane & 15)) * (A_ST * 2) + (lane >> 4) * 16);
    uint32_t ahB = sb + SM_AH(buf) + aOff;
    uint32_t alB = sb + SM_AL(buf) + aOff;
    uint32_t bRow = (uint32_t)(((lane >> 4) & 1) * 8 + (lane & 7));
    uint32_t bCol = (uint32_t)(((lane >> 3) & 1) * 16);
    uint32_t bOff01 = bRow * (A_ST * 2) + bCol;
    uint32_t bOff23 = (bRow + 16) * (A_ST * 2) + bCol;
    uint32_t bhB = sb + SM_BH(buf), blB = sb + SM_BL(buf);
#pragma unroll
    for (int ks = 0; ks < 128; ks += 16) {
        uint32_t kb = (uint32_t)(ks * 2);
        uint32_t ah[4], al[4], bh01[4], bh23[4], bl01[4], bl23[4];
        ldsm_x4(ah[0], ah[1], ah[2], ah[3], ahB + kb);
        ldsm_x4(al[0], al[1], al[2], al[3], alB + kb);
        ldsm_x4(bh01[0], bh01[1], bh01[2], bh01[3], bhB + bOff01 + kb);
        ldsm_x4(bh23[0], bh23[1], bh23[2], bh23[3], bhB + bOff23 + kb);
        ldsm_x4(bl01[0], bl01[1], bl01[2], bl01[3], blB + bOff01 + kb);
        ldsm_x4(bl23[0], bl23[1], bl23[2], bl23[3], blB + bOff23 + kb);
#pragma unroll
        for (int g = 0; g < 4; g++) {
            uint32_t b0h = (g < 2) ? bh01[2 * g]     : bh23[2 * (g - 2)];
            uint32_t b1h = (g < 2) ? bh01[2 * g + 1] : bh23[2 * (g - 2) + 1];
            uint32_t b0l = (g < 2) ? bl01[2 * g]     : bl23[2 * (g - 2)];
            uint32_t b1l = (g < 2) ? bl01[2 * g + 1] : bl23[2 * (g - 2) + 1];
            float* d = acc[g];
            mma16816(d[0], d[1], d[2], d[3], ah[0], ah[1], ah[2], ah[3], b0h, b1h);
            mma16816(d[0], d[1], d[2], d[3], ah[0], ah[1], ah[2], ah[3], b0l, b1l);
            mma16816(d[0], d[1], d[2], d[3], al[0], al[1], al[2], al[3], b0h, b1h);
        }
    }
}

// scan step 1: gates1 = h1 @ Whh1^T + A1 -> LSTM1 + boundary mask. grid=128
__global__ void __launch_bounds__(256) k_lstm1(int t, int rb) {
    extern __shared__ char smem[];
    uint32_t sb = smem_to_u32(smem);
    int tid = threadIdx.x, lane = tid & 31, wid = tid >> 5;
    int hb = blockIdx.x * 8;
    const uint4* Ah4 = (const uint4*)g_h1h[rb];
    const uint4* Al4 = (const uint4*)g_h1l[rb];
    const uint4* Wh4 = (const uint4*)g_Whh1_h;
    const uint4* Wl4 = (const uint4*)g_Whh1_l;

    float acc[4][4];
#pragma unroll
    for (int g = 0; g < 4; g++)
#pragma unroll
        for (int c = 0; c < 4; c++) acc[g][c] = 0.f;

    pf_A(sb, 0, Ah4, Al4, 0, tid);
    pf_B(sb, 0, Wh4, Wl4, hb, 0, tid);
    CP_COMMIT();
    for (int c = 0; c < 8; c++) {
        int buf = c & 1;
        if (c + 1 < 8) {
            pf_A(sb, buf ^ 1, Ah4, Al4, (c + 1) * 16, tid);
            pf_B(sb, buf ^ 1, Wh4, Wl4, hb, (c + 1) * 16, tid);
            CP_COMMIT();
            CP_WAIT1();
        } else {
            CP_WAIT0();
        }
        __syncthreads();
        comp_chunk(sb, buf, wid, lane, acc);
        __syncthreads();
    }

    int wb = rb ^ 1;
    int gr = lane >> 2, tc = lane & 3;
    int h0 = hb + 2 * tc;
#pragma unroll
    for (int rs = 0; rs < 2; rs++) {
        int b = wid * 16 + gr + 8 * rs;
        float s = g_s[b];
        const float* a1 = g_A1 + (size_t)(b * T_ + t) * G4_;
        float2 ai = *(const float2*)&a1[h0];
        float2 af = *(const float2*)&a1[1024 + h0];
        float2 ag = *(const float2*)&a1[2048 + h0];
        float2 ao = *(const float2*)&a1[3072 + h0];
        int idx = b * H_ + h0;
        float2 coldp = *(const float2*)&g_c1[idx];

        float gi0 = acc[0][2 * rs] + ai.x, gi1 = acc[0][2 * rs + 1] + ai.y;
        float gf0 = acc[1][2 * rs] + af.x, gf1 = acc[1][2 * rs + 1] + af.y;
        float gg0 = acc[2][2 * rs] + ag.x, gg1 = acc[2][2 * rs + 1] + ag.y;
        float go0 = acc[3][2 * rs] + ao.x, go1 = acc[3][2 * rs + 1] + ao.y;

        float cn0 = sigf(gf0) * coldp.x + sigf(gi0) * tanhf(gg0);
        float cn1 = sigf(gf1) * coldp.y + sigf(gi1) * tanhf(gg1);
        float hn0 = sigf(go0) * tanhf(cn0);
        float hn1 = sigf(go1) * tanhf(cn1);

        float x20 = hn0 * s,          x21 = hn1 * s;
        float h10 = hn0 * (1.0f - s), h11 = hn1 * (1.0f - s);
        float c10 = cn0 * (1.0f - s), c11 = cn1 * (1.0f - s);

        *(float2*)&g_c1[idx] = make_float2(c10, c11);
        *(float2*)&g_h1f[wb][idx] = make_float2(h10, h11);
        *(uint32_t*)&g_h1h[wb][idx] = pack_hi(h10, h11);
        *(uint32_t*)&g_h1l[wb][idx] = pack_lo(h10, h11);
        *(uint32_t*)&g_x2h[idx] = pack_hi(x20, x21);
        *(uint32_t*)&g_x2l[idx] = pack_lo(x20, x21);
    }
}

// scan step 2: gates2 = x2 @ Wih2^T + h2 @ Whh2^T (K=2048) -> LSTM2.
// grid = 144: [0,128) GEMM+LSTM2; [128,144) boundary gate for t+1 (fp32).
__global__ void __launch_bounds__(256) k_lstm2(int t, int rb, float* __restrict__ out2) {
    if (blockIdx.x >= 128) {
        if (t + 1 >= T_) return;
        int b = (blockIdx.x - 128) * 8 + (threadIdx.x >> 5);
        int lane = threadIdx.x & 31;
        const float* h1 = g_h1f[rb ^ 1] + (size_t)b * H_;
        float u = 0.f;
        for (int h = lane; h < H_; h += 32) u += h1[h] * g_wshv[h];
#pragma unroll
        for (int o = 16; o > 0; o >>= 1) u += __shfl_xor_sync(0xffffffffu, u, o);
        if (lane == 0) {
            u += g_abd[b * T_ + t + 1];
            g_s[b] = rintf(sigf(u));
        }
        return;
    }

    extern __shared__ char smem[];
    uint32_t sb = smem_to_u32(smem);
    int tid = threadIdx.x, lane = tid & 31, wid = tid >> 5;
    int hb = blockIdx.x * 8;

    float acc[4][4];
#pragma unroll
    for (int g = 0; g < 4; g++)
#pragma unroll
        for (int c = 0; c < 4; c++) acc[g][c] = 0.f;

    auto pf_chunk = [&](int c, int buf) {
        bool first = (c < 8);
        const uint4* Ah4 = first ? (const uint4*)g_x2h : (const uint4*)g_h2h[rb];
        const uint4* Al4 = first ? (const uint4*)g_x2l : (const uint4*)g_h2l[rb];
        const uint4* Wh4 = first ? (const uint4*)g_Wih2_h : (const uint4*)g_Whh2_h;
        const uint4* Wl4 = first ? (const uint4*)g_Wih2_l : (const uint4*)g_Whh2_l;
        int kq = (c & 7) * 16;
        pf_A(sb, buf, Ah4, Al4, kq, tid);
        pf_B(sb, buf, Wh4, Wl4, hb, kq, tid);
    };

    pf_chunk(0, 0);
    CP_COMMIT();
    for (int c = 0; c < 16; c++) {
        int buf = c & 1;
        if (c + 1 < 16) {
            pf_chunk(c + 1, buf ^ 1);
            CP_COMMIT();
            CP_WAIT1();
        } else {
            CP_WAIT0();
        }
        __syncthreads();
        comp_chunk(sb, buf, wid, lane, acc);
        __syncthreads();
    }

    int wb = rb ^ 1;
    int gr = lane >> 2, tc = lane & 3;
    int h0 = hb + 2 * tc;
#pragma unroll
    for (int rs = 0; rs < 2; rs++) {
        int b = wid * 16 + gr + 8 * rs;
        int idx = b * H_ + h0;
        float2 coldp = *(const float2*)&g_c2[idx];

        float gi0 = acc[0][2 * rs], gi1 = acc[0][2 * rs + 1];
        float gf0 = acc[1][2 * rs], gf1 = acc[1][2 * rs + 1];
        float gg0 = acc[2][2 * rs], gg1 = acc[2][2 * rs + 1];
        float go0 = acc[3][2 * rs], go1 = acc[3][2 * rs + 1];

        float cn0 = sigf(gf0) * coldp.x + sigf(gi0) * tanhf(gg0);
        float cn1 = sigf(gf1) * coldp.y + sigf(gi1) * tanhf(gg1);
        float hn0 = sigf(go0) * tanhf(cn0);
        float hn1 = sigf(go1) * tanhf(cn1);

        *(float2*)&g_c2[idx] = make_float2(cn0, cn1);
        *(uint32_t*)&g_h2h[wb][idx] = pack_hi(hn0, hn1);
        *(uint32_t*)&g_h2l[wb][idx] = pack_lo(hn0, hn1);
        if (out2) *(float2*)&out2[idx] = make_float2(hn0, hn1);
    }
}

// ---------------- launch ---------------------------------------------------
extern "C" void kernel_launch(void* const* d_in, const int* in_sizes, int n_in,
                              void* d_out, int out_size) {
    const float* video   = (const float*)d_in[0];
    const float* W_embed = (const float*)d_in[1];
    const float* b_embed = (const float*)d_in[2];
    const float* W_ih1   = (const float*)d_in[3];
    const float* W_hh1   = (const float*)d_in[4];
    const float* b1      = (const float*)d_in[5];
    const float* Wsi     = (const float*)d_in[6];
    const float* Wsh     = (const float*)d_in[7];
    const float* b_bd    = (const float*)d_in[8];
    const float* vs      = (const float*)d_in[9];
    const float* W_ih2   = (const float*)d_in[10];
    const float* W_hh2   = (const float*)d_in[11];
    float* out = (float*)d_out;

    bf16 *vidh, *vidl, *Vh, *Vl, *Weh, *Wel, *W1h, *W1l;
    float *pV, *pA1;
    cudaGetSymbolAddress((void**)&vidh, g_vidh);  cudaGetSymbolAddress((void**)&vidl, g_vidl);
    cudaGetSymbolAddress((void**)&Vh, g_Vh);      cudaGetSymbolAddress((void**)&Vl, g_Vl);
    cudaGetSymbolAddress((void**)&Weh, g_Wemb_h); cudaGetSymbolAddress((void**)&Wel, g_Wemb_l);
    cudaGetSymbolAddress((void**)&W1h, g_Wih1_h); cudaGetSymbolAddress((void**)&W1l, g_Wih1_l);
    cudaGetSymbolAddress((void**)&pV, g_V);       cudaGetSymbolAddress((void**)&pA1, g_A1);

    cudaFuncSetAttribute(k_lstm1, cudaFuncAttributeMaxDynamicSharedMemorySize, SMEM_SCAN);
    cudaFuncSetAttribute(k_lstm2, cudaFuncAttributeMaxDynamicSharedMemorySize, SMEM_SCAN);

    // 1) boundary-detector projections (fp32)
    k_proj<<<9, 128>>>(Wsi, Wsh, b_bd, vs);

    // 2) fused split of all fp32 operands into (hi, lo) bf16
    k_split_all<<<SPLIT_TOTAL4 / 256, 256>>>(video, W_embed, W_ih1, W_hh1, W_ih2, W_hh2);

    // 3) embed: V = relu(video @ W_embed^T + b), also emit split-bf16 V
    mm_pre<true, true, true><<<dim3(H_ / 64, (B_ * T_) / 128), 256>>>(
        vidh, vidl, Weh, Wel, b_embed, pV, Vh, Vl, H_, F_);

    // 4) A1 = V @ W_ih1^T + b1
    mm_pre<false, true, false><<<dim3(G4_ / 64, (B_ * T_) / 128), 256>>>(
        Vh, Vl, W1h, W1l, b1, pA1, nullptr, nullptr, G4_, H_);

    // 5) abd + t0 gate + zero state
    k_abd_init<<<1536, 256>>>();

    // 6+) sequential scan (cp.async pipelined HMMA + ldmatrix)
    for (int t = 0; t < T_; t++) {
        int rb = t & 1;
        k_lstm1<<<128, 256, SMEM_SCAN>>>(t, rb);
        k_lstm2<<<144, 256, SMEM_SCAN>>>(t, rb, (t == T_ - 1) ? out : nullptr);
    }
}

// round 11
// speedup vs baseline: 4.1215x; 1.0605x over previous
#include <cuda_runtime.h>
#include <cuda_bf16.h>
#include <stdint.h>
#include <math.h>

#define B_ 128
#define T_ 64
#define F_ 2048
#define H_ 1024
#define M_ 512
#define G4_ 4096

typedef __nv_bfloat16 bf16;

// ---------------- fp32 scratch ---------------------------------------------
__device__ float g_V[B_ * T_ * H_];
__device__ float g_A1[(size_t)B_ * T_ * G4_];
__device__ float g_abd[B_ * T_];
__device__ float g_wsiv[H_], g_wshv[H_];
__device__ float g_bb;
__device__ float g_h1f[2][B_ * H_];
__device__ float g_c1[B_ * H_], g_c2[B_ * H_];
__device__ float g_s[B_];

// ---------------- split-bf16 operands --------------------------------------
__device__ bf16 g_vidh[B_ * T_ * F_], g_vidl[B_ * T_ * F_];
__device__ bf16 g_Vh[B_ * T_ * H_],   g_Vl[B_ * T_ * H_];
__device__ bf16 g_Wemb_h[H_ * F_],    g_Wemb_l[H_ * F_];
__device__ bf16 g_Wih1_h[G4_ * H_],   g_Wih1_l[G4_ * H_];
__device__ bf16 g_Whh1_h[G4_ * H_],   g_Whh1_l[G4_ * H_];
__device__ bf16 g_Wih2_h[G4_ * H_],   g_Wih2_l[G4_ * H_];
__device__ bf16 g_Whh2_h[G4_ * H_],   g_Whh2_l[G4_ * H_];
__device__ bf16 g_h1h[2][B_ * H_],    g_h1l[2][B_ * H_];
__device__ bf16 g_h2h[2][B_ * H_],    g_h2l[2][B_ * H_];
__device__ bf16 g_x2h[B_ * H_],       g_x2l[B_ * H_];

__device__ __forceinline__ float sigf(float x) { return 1.0f / (1.0f + expf(-x)); }
__device__ __forceinline__ uint32_t pack_hi(float x, float y) {
    __nv_bfloat162 t; t.x = __float2bfloat16(x); t.y = __float2bfloat16(y);
    return *(uint32_t*)&t;
}
__device__ __forceinline__ uint32_t pack_lo(float x, float y) {
    bf16 hx = __float2bfloat16(x), hy = __float2bfloat16(y);
    __nv_bfloat162 t;
    t.x = __float2bfloat16(x - __bfloat162float(hx));
    t.y = __float2bfloat16(y - __bfloat162float(hy));
    return *(uint32_t*)&t;
}
__device__ __forceinline__ void mma16816(float& c0, float& c1, float& c2, float& c3,
                                         uint32_t a0, uint32_t a1, uint32_t a2, uint32_t a3,
                                         uint32_t b0, uint32_t b1) {
    asm volatile(
        "mma.sync.aligned.m16n8k16.row.col.f32.bf16.bf16.f32 "
        "{%0,%1,%2,%3},{%4,%5,%6,%7},{%8,%9},{%0,%1,%2,%3};"
        : "+f"(c0), "+f"(c1), "+f"(c2), "+f"(c3)
        : "r"(a0), "r"(a1), "r"(a2), "r"(a3), "r"(b0), "r"(b1));
}
__device__ __forceinline__ void ldsm_x4(uint32_t& r0, uint32_t& r1, uint32_t& r2, uint32_t& r3,
                                        uint32_t addr) {
    asm volatile("ldmatrix.sync.aligned.m8n8.x4.shared.b16 {%0,%1,%2,%3}, [%4];"
                 : "=r"(r0), "=r"(r1), "=r"(r2), "=r"(r3) : "r"(addr));
}
__device__ __forceinline__ uint32_t smem_to_u32(const void* p) {
    uint32_t a;
    asm("{ .reg .u64 t; cvta.to.shared.u64 t, %1; cvt.u32.u64 %0, t; }" : "=r"(a) : "l"(p));
    return a;
}
__device__ __forceinline__ void cpa16(uint32_t dst, const void* src) {
    asm volatile("cp.async.cg.shared.global [%0], [%1], 16;" :: "r"(dst), "l"(src));
}
#define CP_COMMIT() asm volatile("cp.async.commit_group;" ::: "memory")
#define CP_WAIT1()  asm volatile("cp.async.wait_group 1;" ::: "memory")
#define CP_WAIT0()  asm volatile("cp.async.wait_group 0;" ::: "memory")

// ---------------- fused split: all 6 fp32 tensors -> (hi,lo) bf16 -----------
#define SPLIT_TOTAL4 8912896
__global__ void k_split_all(const float* __restrict__ video, const float* __restrict__ W_embed,
                            const float* __restrict__ W_ih1, const float* __restrict__ W_hh1,
                            const float* __restrict__ W_ih2, const float* __restrict__ W_hh2) {
    long i = (long)blockIdx.x * 256 + threadIdx.x;
    const float* src; bf16 *h, *l; long j;
    if (i < 4194304L)       { src = video;   h = g_vidh;   l = g_vidl;   j = i; }
    else if (i < 4718592L)  { src = W_embed; h = g_Wemb_h; l = g_Wemb_l; j = i - 4194304L; }
    else if (i < 5767168L)  { src = W_ih1;   h = g_Wih1_h; l = g_Wih1_l; j = i - 4718592L; }
    else if (i < 6815744L)  { src = W_hh1;   h = g_Whh1_h; l = g_Whh1_l; j = i - 5767168L; }
    else if (i < 7864320L)  { src = W_ih2;   h = g_Wih2_h; l = g_Wih2_l; j = i - 6815744L; }
    else                    { src = W_hh2;   h = g_Whh2_h; l = g_Whh2_l; j = i - 7864320L; }
    float4 v = ((const float4*)src)[j];
    uint2 hp, lp;
    hp.x = pack_hi(v.x, v.y); hp.y = pack_hi(v.z, v.w);
    lp.x = pack_lo(v.x, v.y); lp.y = pack_lo(v.z, v.w);
    ((uint2*)h)[j] = hp;
    ((uint2*)l)[j] = lp;
}

// ---------------- boundary-detector projections ----------------------------
__global__ void k_proj(const float* __restrict__ Wsi, const float* __restrict__ Wsh,
                       const float* __restrict__ b_bd, const float* __restrict__ vs) {
    int blk = blockIdx.x;
    if (blk < 8) {
        int h = blk * 128 + threadIdx.x;
        float s1 = 0.f, s2 = 0.f;
        for (int m = 0; m < M_; m++) {
            float v = vs[m];
            s1 += Wsi[m * H_ + h] * v;
            s2 += Wsh[m * H_ + h] * v;
        }
        g_wsiv[h] = s1;
        g_wshv[h] = s2;
    } else {
        __shared__ float red[128];
        float s = 0.f;
        for (int m = threadIdx.x; m < M_; m += 128) s += b_bd[m] * vs[m];
        red[threadIdx.x] = s;
        __syncthreads();
        for (int st = 64; st > 0; st >>= 1) {
            if (threadIdx.x < st) red[threadIdx.x] += red[threadIdx.x + st];
            __syncthreads();
        }
        if (threadIdx.x == 0) g_bb = red[0];
    }
}

// ========== precompute GEMM: BM128 x BN128 x BK32, warp 64x32, cp.async =====
#define MM_TA    10240                     // one 128x40 bf16 array (bytes)
#define MM_BUF   (4 * MM_TA)               // AH, AL, BH, BL per stage
#define MM_SMEM  (2 * MM_BUF)              // 81920 B

__device__ __forceinline__ void mm_pf(uint32_t sb, int stage,
                                      const uint4* __restrict__ A4h, const uint4* __restrict__ A4l,
                                      const uint4* __restrict__ B4h, const uint4* __restrict__ B4l,
                                      int bm0, int bn0, int kq, int K8, int tid) {
    uint32_t st = sb + stage * MM_BUF;
#pragma unroll
    for (int rep = 0; rep < 2; rep++) {
        int u = tid + 256 * rep;
        int r = u >> 2, q = u & 3;
        uint32_t off = (uint32_t)(r * 80 + q * 16);
        cpa16(st + off,              A4h + (size_t)(bm0 + r) * K8 + kq + q);
        cpa16(st + MM_TA + off,      A4l + (size_t)(bm0 + r) * K8 + kq + q);
        cpa16(st + 2 * MM_TA + off,  B4h + (size_t)(bn0 + r) * K8 + kq + q);
        cpa16(st + 3 * MM_TA + off,  B4l + (size_t)(bn0 + r) * K8 + kq + q);
    }
}

__device__ __forceinline__ void mm_comp(uint32_t sb, int stage, uint32_t aOff, uint32_t bOff,
                                        float acc[4][4][4]) {
    uint32_t st = sb + stage * MM_BUF;
    uint32_t sAH = st, sAL = st + MM_TA, sBH = st + 2 * MM_TA, sBL = st + 3 * MM_TA;
#pragma unroll
    for (int ks = 0; ks < 32; ks += 16) {
        uint32_t kb = (uint32_t)(ks * 2);
        uint32_t bh[2][4], bl[2][4];
#pragma unroll
        for (int p = 0; p < 2; p++) {
            ldsm_x4(bh[p][0], bh[p][1], bh[p][2], bh[p][3], sBH + bOff + p * 1280 + kb);
            ldsm_x4(bl[p][0], bl[p][1], bl[p][2], bl[p][3], sBL + bOff + p * 1280 + kb);
        }
#pragma unroll
        for (int mt = 0; mt < 4; mt++) {
            uint32_t ah[4], al[4];
            ldsm_x4(ah[0], ah[1], ah[2], ah[3], sAH + aOff + mt * 1280 + kb);
            ldsm_x4(al[0], al[1], al[2], al[3], sAL + aOff + mt * 1280 + kb);
#pragma unroll
            for (int nt = 0; nt < 4; nt++) {
                int p = nt >> 1, j = nt & 1;
                float* d = acc[mt][nt];
                mma16816(d[0], d[1], d[2], d[3], ah[0], ah[1], ah[2], ah[3], bh[p][2 * j], bh[p][2 * j + 1]);
                mma16816(d[0], d[1], d[2], d[3], ah[0], ah[1], ah[2], ah[3], bl[p][2 * j], bl[p][2 * j + 1]);
                mma16816(d[0], d[1], d[2], d[3], al[0], al[1], al[2], al[3], bh[p][2 * j], bh[p][2 * j + 1]);
            }
        }
    }
}

template <bool RELU, bool BIAS, bool SPLIT>
__global__ void __launch_bounds__(256) mm_pre(const bf16* __restrict__ Ah, const bf16* __restrict__ Al,
                       const bf16* __restrict__ Bh, const bf16* __restrict__ Bl,
                       const float* __restrict__ bias, float* __restrict__ C,
                       bf16* __restrict__ Ch, bf16* __restrict__ Cl, int N, int K) {
    extern __shared__ char smp[];
    uint32_t sb = smem_to_u32(smp);
    int tid = threadIdx.x, lane = tid & 31, wid = tid >> 5;
    int wm = wid >> 2, wn = wid & 3;
    int gr = lane >> 2, tc = lane & 3;
    int bn0 = blockIdx.x * 128, bm0 = blockIdx.y * 128;
    int K8 = K >> 3;
    const uint4* A4h = (const uint4*)Ah; const uint4* A4l = (const uint4*)Al;
    const uint4* B4h = (const uint4*)Bh; const uint4* B4l = (const uint4*)Bl;

    uint32_t aOff = (uint32_t)((wm * 64 + (lane & 15)) * 80 + (lane >> 4) * 16);
    uint32_t bOff = (uint32_t)((wn * 32 + ((lane >> 4) & 1) * 8 + (lane & 7)) * 80
                               + ((lane >> 3) & 1) * 16);

    float acc[4][4][4];
#pragma unroll
    for (int a = 0; a < 4; a++)
#pragma unroll
        for (int b = 0; b < 4; b++)
#pragma unroll
            for (int c = 0; c < 4; c++) acc[a][b][c] = 0.f;

    int nc = K >> 5;
    mm_pf(sb, 0, A4h, A4l, B4h, B4l, bm0, bn0, 0, K8, tid);
    CP_COMMIT();
    for (int c = 0; c < nc; c++) {
        int stg = c & 1;
        if (c + 1 < nc) {
            mm_pf(sb, stg ^ 1, A4h, A4l, B4h, B4l, bm0, bn0, (c + 1) * 4, K8, tid);
            CP_COMMIT();
            CP_WAIT1();
        } else {
            CP_WAIT0();
        }
        __syncthreads();
        mm_comp(sb, stg, aOff, bOff, acc);
        __syncthreads();
    }

#pragma unroll
    for (int mt = 0; mt < 4; mt++)
#pragma unroll
        for (int nt = 0; nt < 4; nt++) {
            int row0 = bm0 + wm * 64 + mt * 16 + gr;
            int col = bn0 + wn * 32 + nt * 8 + 2 * tc;
            float2 bs = BIAS ? *(const float2*)&bias[col] : make_float2(0.f, 0.f);
#pragma unroll
            for (int rs = 0; rs < 2; rs++) {
                int row = row0 + 8 * rs;
                float v0 = acc[mt][nt][2 * rs] + bs.x;
                float v1 = acc[mt][nt][2 * rs + 1] + bs.y;
                if (RELU) { v0 = fmaxf(v0, 0.f); v1 = fmaxf(v1, 0.f); }
                *(float2*)&C[(size_t)row * N + col] = make_float2(v0, v1);
                if (SPLIT) {
                    *(uint32_t*)&Ch[(size_t)row * N + col] = pack_hi(v0, v1);
                    *(uint32_t*)&Cl[(size_t)row * N + col] = pack_lo(v0, v1);
                }
            }
        }
}

// ---------------- fused abd + t0-gate + state init -------------------------
__global__ void k_abd_init() {
    if (blockIdx.x < 1024) {
        int r = blockIdx.x * 8 + (threadIdx.x >> 5);
        int lane = threadIdx.x & 31;
        const float* vr = g_V + (size_t)r * H_;
        float s = 0.f;
        for (int h = lane; h < H_; h += 32) s += vr[h] * g_wsiv[h];
#pragma unroll
        for (int o = 16; o > 0; o >>= 1) s += __shfl_xor_sync(0xffffffffu, s, o);
        if (lane == 0) {
            float u = s + g_bb;
            g_abd[r] = u;
            if ((r & (T_ - 1)) == 0)
                g_s[r >> 6] = rintf(sigf(u));
        }
    } else {
        int i = (blockIdx.x - 1024) * 256 + threadIdx.x;
        if (i < B_ * H_) {
            g_c1[i] = 0.f; g_c2[i] = 0.f;
            bf16 z = __float2bfloat16(0.f);
            g_h1h[0][i] = z; g_h1l[0][i] = z;
            g_h2h[0][i] = z; g_h2l[0][i] = z;
        }
    }
}

// ================= cp.async pipelined scan kernels (BK=128, ldmatrix) =======
#define A_ST   136                               // bf16 stride (272 B rows)
#define A_TILE (128 * A_ST * 2)                  // 34816 B
#define B_TILE (32 * A_ST * 2)                   // 8704 B
#define BUF_SZ (2 * A_TILE + 2 * B_TILE)         // 87040 B
#define SM_AH(b) ((b) * BUF_SZ)
#define SM_AL(b) ((b) * BUF_SZ + A_TILE)
#define SM_BH(b) ((b) * BUF_SZ + 2 * A_TILE)
#define SM_BL(b) ((b) * BUF_SZ + 2 * A_TILE + B_TILE)
#define SMEM_SCAN (2 * BUF_SZ)                   // 174080 B

__device__ __forceinline__ void pf_A(uint32_t sb, int buf,
                                     const uint4* __restrict__ Ah4,
                                     const uint4* __restrict__ Al4,
                                     int kq, int tid) {
#pragma unroll
    for (int rep = 0; rep < 8; rep++) {
        int u = tid + 256 * rep;
        int r = u >> 4, q = u & 15;
        uint32_t off = (uint32_t)(r * (A_ST * 2) + q * 16);
        cpa16(sb + SM_AH(buf) + off, Ah4 + (size_t)r * 128 + kq + q);
        cpa16(sb + SM_AL(buf) + off, Al4 + (size_t)r * 128 + kq + q);
    }
}
__device__ __forceinline__ void pf_B(uint32_t sb, int buf,
                                     const uint4* __restrict__ Wh4,
                                     const uint4* __restrict__ Wl4,
                                     int hb, int kq, int tid) {
#pragma unroll
    for (int rep = 0; rep < 2; rep++) {
        int u = tid + 256 * rep;
        int n = u >> 4, q = u & 15;
        int wr = (n >> 3) * H_ + hb + (n & 7);
        uint32_t off = (uint32_t)(n * (A_ST * 2) + q * 16);
        cpa16(sb + SM_BH(buf) + off, Wh4 + (size_t)wr * 128 + kq + q);
        cpa16(sb + SM_BL(buf) + off, Wl4 + (size_t)wr * 128 + kq + q);
    }
}
__device__ __forceinline__ void comp_chunk(uint32_t sb, int buf, int wid, int lane,
                                           float acc[4][4]) {
    uint32_t aOff = (uint32_t)((wid * 16 + (lane & 15)) * (A_ST * 2) + (lane >> 4) * 16);
    uint32_t ahB = sb + SM_AH(buf) + aOff;
    uint32_t alB = sb + SM_AL(buf) + aOff;
    uint32_t bRow = (uint32_t)(((lane >> 4) & 1) * 8 + (lane & 7));
    uint32_t bCol = (uint32_t)(((lane >> 3) & 1) * 16);
    uint32_t bOff01 = bRow * (A_ST * 2) + bCol;
    uint32_t bOff23 = (bRow + 16) * (A_ST * 2) + bCol;
    uint32_t bhB = sb + SM_BH(buf), blB = sb + SM_BL(buf);
#pragma unroll
    for (int ks = 0; ks < 128; ks += 16) {
        uint32_t kb = (uint32_t)(ks * 2);
        uint32_t ah[4], al[4], bh01[4], bh23[4], bl01[4], bl23[4];
        ldsm_x4(ah[0], ah[1], ah[2], ah[3], ahB + kb);
        ldsm_x4(al[0], al[1], al[2], al[3], alB + kb);
        ldsm_x4(bh01[0], bh01[1], bh01[2], bh01[3], bhB + bOff01 + kb);
        ldsm_x4(bh23[0], bh23[1], bh23[2], bh23[3], bhB + bOff23 + kb);
        ldsm_x4(bl01[0], bl01[1], bl01[2], bl01[3], blB + bOff01 + kb);
        ldsm_x4(bl23[0], bl23[1], bl23[2], bl23[3], blB + bOff23 + kb);
#pragma unroll
        for (int g = 0; g < 4; g++) {
            uint32_t b0h = (g < 2) ? bh01[2 * g]     : bh23[2 * (g - 2)];
            uint32_t b1h = (g < 2) ? bh01[2 * g + 1] : bh23[2 * (g - 2) + 1];
            uint32_t b0l = (g < 2) ? bl01[2 * g]     : bl23[2 * (g - 2)];
            uint32_t b1l = (g < 2) ? bl01[2 * g + 1] : bl23[2 * (g - 2) + 1];
            float* d = acc[g];
            mma16816(d[0], d[1], d[2], d[3], ah[0], ah[1], ah[2], ah[3], b0h, b1h);
            mma16816(d[0], d[1], d[2], d[3], ah[0], ah[1], ah[2], ah[3], b0l, b1l);
            mma16816(d[0], d[1], d[2], d[3], al[0], al[1], al[2], al[3], b0h, b1h);
        }
    }
}

// scan step 1: gates1 = h1 @ Whh1^T + A1 -> LSTM1 + boundary mask. grid=128
__global__ void __launch_bounds__(256) k_lstm1(int t, int rb) {
    extern __shared__ char smem[];
    uint32_t sb = smem_to_u32(smem);
    int tid = threadIdx.x, lane = tid & 31, wid = tid >> 5;
    int hb = blockIdx.x * 8;
    const uint4* Ah4 = (const uint4*)g_h1h[rb];
    const uint4* Al4 = (const uint4*)g_h1l[rb];
    const uint4* Wh4 = (const uint4*)g_Whh1_h;
    const uint4* Wl4 = (const uint4*)g_Whh1_l;

    float acc[4][4];
#pragma unroll
    for (int g = 0; g < 4; g++)
#pragma unroll
        for (int c = 0; c < 4; c++) acc[g][c] = 0.f;

    pf_A(sb, 0, Ah4, Al4, 0, tid);
    pf_B(sb, 0, Wh4, Wl4, hb, 0, tid);
    CP_COMMIT();
    for (int c = 0; c < 8; c++) {
        int buf = c & 1;
        if (c + 1 < 8) {
            pf_A(sb, buf ^ 1, Ah4, Al4, (c + 1) * 16, tid);
            pf_B(sb, buf ^ 1, Wh4, Wl4, hb, (c + 1) * 16, tid);
            CP_COMMIT();
            CP_WAIT1();
        } else {
            CP_WAIT0();
        }
        __syncthreads();
        comp_chunk(sb, buf, wid, lane, acc);
        __syncthreads();
    }

    int wb = rb ^ 1;
    int gr = lane >> 2, tc = lane & 3;
    int h0 = hb + 2 * tc;
#pragma unroll
    for (int rs = 0; rs < 2; rs++) {
        int b = wid * 16 + gr + 8 * rs;
        float s = g_s[b];
        const float* a1 = g_A1 + (size_t)(b * T_ + t) * G4_;
        float2 ai = *(const float2*)&a1[h0];
        float2 af = *(const float2*)&a1[1024 + h0];
        float2 ag = *(const float2*)&a1[2048 + h0];
        float2 ao = *(const float2*)&a1[3072 + h0];
        int idx = b * H_ + h0;
        float2 coldp = *(const float2*)&g_c1[idx];

        float gi0 = acc[0][2 * rs] + ai.x, gi1 = acc[0][2 * rs + 1] + ai.y;
        float gf0 = acc[1][2 * rs] + af.x, gf1 = acc[1][2 * rs + 1] + af.y;
        float gg0 = acc[2][2 * rs] + ag.x, gg1 = acc[2][2 * rs + 1] + ag.y;
        float go0 = acc[3][2 * rs] + ao.x, go1 = acc[3][2 * rs + 1] + ao.y;

        float cn0 = sigf(gf0) * coldp.x + sigf(gi0) * tanhf(gg0);
        float cn1 = sigf(gf1) * coldp.y + sigf(gi1) * tanhf(gg1);
        float hn0 = sigf(go0) * tanhf(cn0);
        float hn1 = sigf(go1) * tanhf(cn1);

        float x20 = hn0 * s,          x21 = hn1 * s;
        float h10 = hn0 * (1.0f - s), h11 = hn1 * (1.0f - s);
        float c10 = cn0 * (1.0f - s), c11 = cn1 * (1.0f - s);

        *(float2*)&g_c1[idx] = make_float2(c10, c11);
        *(float2*)&g_h1f[wb][idx] = make_float2(h10, h11);
        *(uint32_t*)&g_h1h[wb][idx] = pack_hi(h10, h11);
        *(uint32_t*)&g_h1l[wb][idx] = pack_lo(h10, h11);
        *(uint32_t*)&g_x2h[idx] = pack_hi(x20, x21);
        *(uint32_t*)&g_x2l[idx] = pack_lo(x20, x21);
    }
}

// scan step 2: gates2 = x2 @ Wih2^T + h2 @ Whh2^T (K=2048) -> LSTM2.
// grid = 144: [0,128) GEMM+LSTM2; [128,144) boundary gate for t+1 (fp32).
__global__ void __launch_bounds__(256) k_lstm2(int t, int rb, float* __restrict__ out2) {
    if (blockIdx.x >= 128) {
        if (t + 1 >= T_) return;
        int b = (blockIdx.x - 128) * 8 + (threadIdx.x >> 5);
        int lane = threadIdx.x & 31;
        const float* h1 = g_h1f[rb ^ 1] + (size_t)b * H_;
        float u = 0.f;
        for (int h = lane; h < H_; h += 32) u += h1[h] * g_wshv[h];
#pragma unroll
        for (int o = 16; o > 0; o >>= 1) u += __shfl_xor_sync(0xffffffffu, u, o);
        if (lane == 0) {
            u += g_abd[b * T_ + t + 1];
            g_s[b] = rintf(sigf(u));
        }
        return;
    }

    extern __shared__ char smem[];
    uint32_t sb = smem_to_u32(smem);
    int tid = threadIdx.x, lane = tid & 31, wid = tid >> 5;
    int hb = blockIdx.x * 8;

    float acc[4][4];
#pragma unroll
    for (int g = 0; g < 4; g++)
#pragma unroll
        for (int c = 0; c < 4; c++) acc[g][c] = 0.f;

    auto pf_chunk = [&](int c, int buf) {
        bool first = (c < 8);
        const uint4* Ah4 = first ? (const uint4*)g_x2h : (const uint4*)g_h2h[rb];
        const uint4* Al4 = first ? (const uint4*)g_x2l : (const uint4*)g_h2l[rb];
        const uint4* Wh4 = first ? (const uint4*)g_Wih2_h : (const uint4*)g_Whh2_h;
        const uint4* Wl4 = first ? (const uint4*)g_Wih2_l : (const uint4*)g_Whh2_l;
        int kq = (c & 7) * 16;
        pf_A(sb, buf, Ah4, Al4, kq, tid);
        pf_B(sb, buf, Wh4, Wl4, hb, kq, tid);
    };

    pf_chunk(0, 0);
    CP_COMMIT();
    for (int c = 0; c < 16; c++) {
        int buf = c & 1;
        if (c + 1 < 16) {
            pf_chunk(c + 1, buf ^ 1);
            CP_COMMIT();
            CP_WAIT1();
        } else {
            CP_WAIT0();
        }
        __syncthreads();
        comp_chunk(sb, buf, wid, lane, acc);
        __syncthreads();
    }

    int wb = rb ^ 1;
    int gr = lane >> 2, tc = lane & 3;
    int h0 = hb + 2 * tc;
#pragma unroll
    for (int rs = 0; rs < 2; rs++) {
        int b = wid * 16 + gr + 8 * rs;
        int idx = b * H_ + h0;
        float2 coldp = *(const float2*)&g_c2[idx];

        float gi0 = acc[0][2 * rs], gi1 = acc[0][2 * rs + 1];
        float gf0 = acc[1][2 * rs], gf1 = acc[1][2 * rs + 1];
        float gg0 = acc[2][2 * rs], gg1 = acc[2][2 * rs + 1];
        float go0 = acc[3][2 * rs], go1 = acc[3][2 * rs + 1];

        float cn0 = sigf(gf0) * coldp.x + sigf(gi0) * tanhf(gg0);
        float cn1 = sigf(gf1) * coldp.y + sigf(gi1) * tanhf(gg1);
        float hn0 = sigf(go0) * tanhf(cn0);
        float hn1 = sigf(go1) * tanhf(cn1);

        *(float2*)&g_c2[idx] = make_float2(cn0, cn1);
        *(uint32_t*)&g_h2h[wb][idx] = pack_hi(hn0, hn1);
        *(uint32_t*)&g_h2l[wb][idx] = pack_lo(hn0, hn1);
        if (out2) *(float2*)&out2[idx] = make_float2(hn0, hn1);
    }
}

// ---------------- launch ---------------------------------------------------
extern "C" void kernel_launch(void* const* d_in, const int* in_sizes, int n_in,
                              void* d_out, int out_size) {
    const float* video   = (const float*)d_in[0];
    const float* W_embed = (const float*)d_in[1];
    const float* b_embed = (const float*)d_in[2];
    const float* W_ih1   = (const float*)d_in[3];
    const float* W_hh1   = (const float*)d_in[4];
    const float* b1      = (const float*)d_in[5];
    const float* Wsi     = (const float*)d_in[6];
    const float* Wsh     = (const float*)d_in[7];
    const float* b_bd    = (const float*)d_in[8];
    const float* vs      = (const float*)d_in[9];
    const float* W_ih2   = (const float*)d_in[10];
    const float* W_hh2   = (const float*)d_in[11];
    float* out = (float*)d_out;

    bf16 *vidh, *vidl, *Vh, *Vl, *Weh, *Wel, *W1h, *W1l;
    float *pV, *pA1;
    cudaGetSymbolAddress((void**)&vidh, g_vidh);  cudaGetSymbolAddress((void**)&vidl, g_vidl);
    cudaGetSymbolAddress((void**)&Vh, g_Vh);      cudaGetSymbolAddress((void**)&Vl, g_Vl);
    cudaGetSymbolAddress((void**)&Weh, g_Wemb_h); cudaGetSymbolAddress((void**)&Wel, g_Wemb_l);
    cudaGetSymbolAddress((void**)&W1h, g_Wih1_h); cudaGetSymbolAddress((void**)&W1l, g_Wih1_l);
    cudaGetSymbolAddress((void**)&pV, g_V);       cudaGetSymbolAddress((void**)&pA1, g_A1);

    cudaFuncSetAttribute(k_lstm1, cudaFuncAttributeMaxDynamicSharedMemorySize, SMEM_SCAN);
    cudaFuncSetAttribute(k_lstm2, cudaFuncAttributeMaxDynamicSharedMemorySize, SMEM_SCAN);
    cudaFuncSetAttribute(mm_pre<true, true, true>,
                         cudaFuncAttributeMaxDynamicSharedMemorySize, MM_SMEM);
    cudaFuncSetAttribute(mm_pre<false, true, false>,
                         cudaFuncAttributeMaxDynamicSharedMemorySize, MM_SMEM);

    // 1) boundary-detector projections (fp32)
    k_proj<<<9, 128>>>(Wsi, Wsh, b_bd, vs);

    // 2) fused split of all fp32 operands into (hi, lo) bf16
    k_split_all<<<SPLIT_TOTAL4 / 256, 256>>>(video, W_embed, W_ih1, W_hh1, W_ih2, W_hh2);

    // 3) embed: V = relu(video @ W_embed^T + b), also emit split-bf16 V
    mm_pre<true, true, true><<<dim3(H_ / 128, 64), 256, MM_SMEM>>>(
        vidh, vidl, Weh, Wel, b_embed, pV, Vh, Vl, H_, F_);

    // 4) A1 = V @ W_ih1^T + b1
    mm_pre<false, true, false><<<dim3(G4_ / 128, 64), 256, MM_SMEM>>>(
        Vh, Vl, W1h, W1l, b1, pA1, nullptr, nullptr, G4_, H_);

    // 5) abd + t0 gate + zero state
    k_abd_init<<<1536, 256>>>();

    // 6+) sequential scan (cp.async pipelined HMMA + ldmatrix)
    for (int t = 0; t < T_; t++) {
        int rb = t & 1;
        k_lstm1<<<128, 256, SMEM_SCAN>>>(t, rb);
        k_lstm2<<<144, 256, SMEM_SCAN>>>(t, rb, (t == T_ - 1) ? out : nullptr);
    }
}